// round 14
// baseline (speedup 1.0000x reference)
#include <cuda_runtime.h>
#include <cuda_fp16.h>
#include <math.h>
#include <stdint.h>

#define B_  4
#define T_  24
#define N_  2048
#define D_  256
#define H_  8
#define HD_ 32
#define MTOK (B_*T_*N_)           // 196608 tokens
#define ELEMS ((size_t)MTOK * D_) // 50,331,648

// Scratch (device globals; allocation-free per harness rules). All fp16.
__device__ __half g_q [ELEMS];
__device__ __half g_k [ELEMS];
__device__ __half g_v [ELEMS];
__device__ __half g_os[ELEMS];
__device__ __half g_ot[ELEMS];
__device__ __half g_wqh[768*256];
__device__ __half g_woh[256*512];

// ---------------------------------------------------------------------------
// helpers
// ---------------------------------------------------------------------------
__device__ __forceinline__ uint32_t smem_u32(const void* p) {
    uint32_t a;
    asm("{ .reg .u64 t; cvta.to.shared.u64 t, %1; cvt.u32.u64 %0, t; }"
        : "=r"(a) : "l"(p));
    return a;
}
__device__ __forceinline__ uint32_t f2h2(float a, float b) {
    __half2 h = __floats2half2_rn(a, b);
    return *(uint32_t*)&h;
}
__device__ __forceinline__ uint2 f4h(float4 v) {
    return make_uint2(f2h2(v.x, v.y), f2h2(v.z, v.w));
}
__device__ __forceinline__ float2 h2f2(uint32_t h) {
    return __half22float2(*(__half2*)&h);
}
__device__ __forceinline__ void ldm_x4(uint32_t* r, uint32_t addr) {
    asm volatile("ldmatrix.sync.aligned.m8n8.x4.shared.b16 {%0,%1,%2,%3}, [%4];"
                 : "=r"(r[0]), "=r"(r[1]), "=r"(r[2]), "=r"(r[3]) : "r"(addr));
}
__device__ __forceinline__ void ldm_x4_t(uint32_t* r, uint32_t addr) {
    asm volatile("ldmatrix.sync.aligned.m8n8.x4.trans.shared.b16 {%0,%1,%2,%3}, [%4];"
                 : "=r"(r[0]), "=r"(r[1]), "=r"(r[2]), "=r"(r[3]) : "r"(addr));
}
#define MMA_F16(d, a0, a1, a2, a3, b0, b1)                                    \
    asm volatile("mma.sync.aligned.m16n8k16.row.col.f32.f16.f16.f32 "         \
                 "{%0,%1,%2,%3}, {%4,%5,%6,%7}, {%8,%9}, {%0,%1,%2,%3};"      \
                 : "+f"(d[0]), "+f"(d[1]), "+f"(d[2]), "+f"(d[3])             \
                 : "r"(a0), "r"(a1), "r"(a2), "r"(a3), "r"(b0), "r"(b1))

// Row strides: 80B (chunk tiles) and 528B (resident A). Both ≡16 (mod 128).
#define CH_STRIDE 80
#define AR_STRIDE 528
#define AR_BYTES  (128*AR_STRIDE)

// ---------------------------------------------------------------------------
// weight pre-conversion: f32 -> f16 (once per launch)
// ---------------------------------------------------------------------------
__global__ void cvt_weights_kernel(const float* __restrict__ wq,
                                   const float* __restrict__ wo,
                                   __half* __restrict__ wqh,
                                   __half* __restrict__ woh)
{
    int i = blockIdx.x * blockDim.x + threadIdx.x;
    const int NQ = 768 * 256 / 2;
    const int NO = 256 * 512 / 2;
    if (i < NQ) {
        float2 f = *(const float2*)(wq + i * 2);
        *(uint32_t*)(wqh + i * 2) = f2h2(f.x, f.y);
    } else if (i < NQ + NO) {
        int j = i - NQ;
        float2 f = *(const float2*)(wo + j * 2);
        *(uint32_t*)(woh + j * 2) = f2h2(f.x, f.y);
    }
}

// ===========================================================================
// GEMM1 (A-resident, fp16): qkv[M,768] = x[M,256] * w_qkv[768,256]^T
// CTA: 128 m rows resident; inner loop = 3 n-tiles of 256 x 8 k-chunks.
// 8 warps 2m x 4n, warp tile 64x64. Fused q/k per-head L2 norm.
// ===========================================================================
#define G1_NBUF (256*CH_STRIDE)              // 20480
#define G1_SMEM (AR_BYTES + 2*G1_NBUF)       // 108544

__global__ __launch_bounds__(256, 1)
void gemm_qkv_kernel(const float* __restrict__ A, const __half* __restrict__ Bw,
                     __half* __restrict__ outq, __half* __restrict__ outk,
                     __half* __restrict__ outv)
{
    extern __shared__ __align__(16) char smem[];
    const uint32_t sbase = smem_u32(smem);
    const int tid  = threadIdx.x;
    const int lane = tid & 31;
    const int wid  = tid >> 5;
    const int wm   = wid & 1;                 // m offset wm*64
    const int wn   = wid >> 1;                // n offset wn*64 (0..3)
    const int m0   = blockIdx.x * 128;

    const int ar = tid >> 1;
    const int ac = tid & 1;
    const int fr = lane & 15;
    const int fc = (lane >> 4) * 16;
    const int r  = lane >> 2;
    const int c2 = (lane & 3) << 1;

    // ---- prologue: A (128x256 f32) -> resident fp16 smem, once ----
    #pragma unroll
    for (int j = 0; j < 8; j++) {
        const float* ap = A + (size_t)(m0 + ar) * 256 + (ac * 8 + j) * 16;
        uint2 h0 = f4h(*(const float4*)(ap + 0));
        uint2 h1 = f4h(*(const float4*)(ap + 4));
        uint2 h2 = f4h(*(const float4*)(ap + 8));
        uint2 h3 = f4h(*(const float4*)(ap + 12));
        char* dst = smem + ar * AR_STRIDE + (ac * 8 + j) * 32;
        *(uint4*)(dst)      = make_uint4(h0.x, h0.y, h1.x, h1.y);
        *(uint4*)(dst + 16) = make_uint4(h2.x, h2.y, h3.x, h3.y);
    }

    // ---- B loader: one thread per n-row (256 rows x 32 halfs = 64B/thread) ----
    uint4 rb[4];
    auto ldgB = [&](int it) {
        const int nt0 = it >> 3, kt = it & 7;
        const __half* bp = Bw + (size_t)(nt0 * 256 + tid) * 256 + kt * 32;
        #pragma unroll
        for (int j = 0; j < 4; j++) rb[j] = *(const uint4*)(bp + j * 8);
    };
    auto stsB = [&](int buf) {
        char* dst = smem + AR_BYTES + buf * G1_NBUF + tid * CH_STRIDE;
        #pragma unroll
        for (int j = 0; j < 4; j++) *(uint4*)(dst + j * 16) = rb[j];
    };

    float acc[4][8][4];
    #pragma unroll
    for (int i = 0; i < 4; i++)
        #pragma unroll
        for (int j = 0; j < 8; j++)
            #pragma unroll
            for (int c = 0; c < 4; c++) acc[i][j][c] = 0.f;

    ldgB(0);
    stsB(0);
    __syncthreads();

    #pragma unroll 1
    for (int it = 0; it < 24; it++) {
        if (it + 1 < 24) ldgB(it + 1);

        // ---- compute: resident-A chunk (it&7) x B buffer (it&1) ----
        {
            const int kt = it & 7;
            const uint32_t abase = sbase + kt * 64;
            const uint32_t bbase = sbase + AR_BYTES + (it & 1) * G1_NBUF;
            #pragma unroll
            for (int s = 0; s < 2; s++) {
                uint32_t af[4][4], bf[4][4];
                #pragma unroll
                for (int mt = 0; mt < 4; mt++) {
                    int row = wm * 64 + mt * 16 + fr;
                    ldm_x4(af[mt], abase + row * AR_STRIDE + s * 32 + fc);
                }
                #pragma unroll
                for (int bi = 0; bi < 4; bi++) {
                    int row = wn * 64 + bi * 16 + fr;
                    ldm_x4(bf[bi], bbase + row * CH_STRIDE + s * 32 + fc);
                }
                #pragma unroll
                for (int mt = 0; mt < 4; mt++)
                    #pragma unroll
                    for (int nt2 = 0; nt2 < 8; nt2++) {
                        int bi = nt2 >> 1, od = nt2 & 1;
                        MMA_F16(acc[mt][nt2],
                                af[mt][0], af[mt][1], af[mt][2], af[mt][3],
                                bf[bi][od], bf[bi][od + 2]);
                    }
            }
        }

        // ---- per-n-tile epilogue (each tile is exactly q, k, or v) ----
        if ((it & 7) == 7) {
            const int sel = it >> 3;

            if (sel < 2) {   // q or k: per-head L2 norm; warp n=64 = 2 head chunks
                #pragma unroll
                for (int mt = 0; mt < 4; mt++) {
                    #pragma unroll
                    for (int g = 0; g < 2; g++) {
                        float sslo = 0.f, sshi = 0.f;
                        #pragma unroll
                        for (int j = 0; j < 4; j++) {
                            float* a = acc[mt][g * 4 + j];
                            sslo = fmaf(a[0], a[0], sslo);
                            sslo = fmaf(a[1], a[1], sslo);
                            sshi = fmaf(a[2], a[2], sshi);
                            sshi = fmaf(a[3], a[3], sshi);
                        }
                        sslo += __shfl_xor_sync(0xffffffffu, sslo, 1);
                        sslo += __shfl_xor_sync(0xffffffffu, sslo, 2);
                        sshi += __shfl_xor_sync(0xffffffffu, sshi, 1);
                        sshi += __shfl_xor_sync(0xffffffffu, sshi, 2);
                        float slo = 1.f / fmaxf(sqrtf(sslo), 1e-12f);
                        float shi = 1.f / fmaxf(sqrtf(sshi), 1e-12f);
                        #pragma unroll
                        for (int j = 0; j < 4; j++) {
                            float* a = acc[mt][g * 4 + j];
                            a[0] *= slo; a[1] *= slo;
                            a[2] *= shi; a[3] *= shi;
                        }
                    }
                }
            }

            __half* dst = (sel == 0) ? outq : ((sel == 1) ? outk : outv);
            #pragma unroll
            for (int mt = 0; mt < 4; mt++) {
                int m = m0 + wm * 64 + mt * 16 + r;
                #pragma unroll
                for (int nt2 = 0; nt2 < 8; nt2++) {
                    int col = wn * 64 + nt2 * 8 + c2;
                    float* a = acc[mt][nt2];
                    *(uint32_t*)(dst + (size_t)m * 256 + col)       = f2h2(a[0], a[1]);
                    *(uint32_t*)(dst + (size_t)(m + 8) * 256 + col) = f2h2(a[2], a[3]);
                    a[0] = a[1] = a[2] = a[3] = 0.f;
                }
            }
        }

        if (it + 1 < 24) stsB((it + 1) & 1);
        __syncthreads();
    }
}

// ===========================================================================
// GEMM2 (fp16 in / f32 out): out[M,256] = [os|ot][M,512] * w_out[256,512]^T + b
// CTA tile 128 x 256 (full N). 8 warps 2m x 4n, warp tile 64x64. K=512.
// ===========================================================================
#define G2A_BUF (128*CH_STRIDE)              // 10240
#define G2B_BUF (256*CH_STRIDE)              // 20480
#define G2_SMEM (2*G2A_BUF + 2*G2B_BUF + 1024)  // 62464

__global__ __launch_bounds__(256, 1)
void gemm_out_kernel(const __half* __restrict__ A0, const __half* __restrict__ A1,
                     const __half* __restrict__ Bw,
                     const float* __restrict__ bias,
                     float* __restrict__ out)
{
    extern __shared__ __align__(16) char smem[];
    const uint32_t sbase = smem_u32(smem);
    const int tid  = threadIdx.x;
    const int lane = tid & 31;
    const int wid  = tid >> 5;
    const int wm   = wid & 1;
    const int wn   = wid >> 1;
    const int m0   = blockIdx.x * 128;

    const int ar = tid >> 1;
    const int ac = tid & 1;
    const int fr = lane & 15;
    const int fc = (lane >> 4) * 16;
    const int r  = lane >> 2;
    const int c2 = (lane & 3) << 1;

    float* s_bias = (float*)(smem + 2 * G2A_BUF + 2 * G2B_BUF);
    s_bias[tid] = bias[tid];

    uint4 ua0, ua1, rb[4];
    auto ldg = [&](int kt) {
        const int k0 = kt * 32;
        const __half* Asrc = (k0 < 256) ? A0 : A1;
        const int kc = k0 & 255;
        const __half* ap = Asrc + (size_t)(m0 + ar) * 256 + kc + ac * 16;
        ua0 = *(const uint4*)(ap);
        ua1 = *(const uint4*)(ap + 8);
        const __half* bp = Bw + (size_t)tid * 512 + k0;
        #pragma unroll
        for (int j = 0; j < 4; j++) rb[j] = *(const uint4*)(bp + j * 8);
    };
    auto sts = [&](int buf) {
        char* da = smem + buf * G2A_BUF + ar * CH_STRIDE + ac * 32;
        *(uint4*)(da)      = ua0;
        *(uint4*)(da + 16) = ua1;
        char* db = smem + 2 * G2A_BUF + buf * G2B_BUF + tid * CH_STRIDE;
        #pragma unroll
        for (int j = 0; j < 4; j++) *(uint4*)(db + j * 16) = rb[j];
    };

    float acc[4][8][4];
    #pragma unroll
    for (int i = 0; i < 4; i++)
        #pragma unroll
        for (int j = 0; j < 8; j++)
            #pragma unroll
            for (int c = 0; c < 4; c++) acc[i][j][c] = 0.f;

    ldg(0);
    sts(0);
    __syncthreads();

    #pragma unroll 1
    for (int kt = 0; kt < 16; kt++) {
        if (kt + 1 < 16) ldg(kt + 1);

        {
            const uint32_t abase = sbase + (kt & 1) * G2A_BUF;
            const uint32_t bbase = sbase + 2 * G2A_BUF + (kt & 1) * G2B_BUF;
            #pragma unroll
            for (int s = 0; s < 2; s++) {
                uint32_t af[4][4], bf[4][4];
                #pragma unroll
                for (int mt = 0; mt < 4; mt++) {
                    int row = wm * 64 + mt * 16 + fr;
                    ldm_x4(af[mt], abase + row * CH_STRIDE + s * 32 + fc);
                }
                #pragma unroll
                for (int bi = 0; bi < 4; bi++) {
                    int row = wn * 64 + bi * 16 + fr;
                    ldm_x4(bf[bi], bbase + row * CH_STRIDE + s * 32 + fc);
                }
                #pragma unroll
                for (int mt = 0; mt < 4; mt++)
                    #pragma unroll
                    for (int nt2 = 0; nt2 < 8; nt2++) {
                        int bi = nt2 >> 1, od = nt2 & 1;
                        MMA_F16(acc[mt][nt2],
                                af[mt][0], af[mt][1], af[mt][2], af[mt][3],
                                bf[bi][od], bf[bi][od + 2]);
                    }
            }
        }

        if (kt + 1 < 16) sts((kt + 1) & 1);
        __syncthreads();
    }

    #pragma unroll
    for (int mt = 0; mt < 4; mt++) {
        int m = m0 + wm * 64 + mt * 16 + r;
        #pragma unroll
        for (int nt = 0; nt < 8; nt++) {
            int n = wn * 64 + nt * 8 + c2;
            float* a = acc[mt][nt];
            float b0 = s_bias[n], b1 = s_bias[n + 1];
            *(float2*)(out + (size_t)m * 256 + n)       = make_float2(a[0] + b0, a[1] + b1);
            *(float2*)(out + (size_t)(m + 8) * 256 + n) = make_float2(a[2] + b0, a[3] + b1);
        }
    }
}

// ---------------------------------------------------------------------------
// Spatial linear attention (attend over N=2048). Block = (bt, h), 8 warps.
// Phase 1: mma via ldmatrix.trans — kvs = k^T [v | 1], kss = column 32.
// Phase 2: mma with B = [kvs^T | kss].
// ---------------------------------------------------------------------------
#define BVS 40   // half stride (80 B) for phase-2 B / q staging rows
#define KST_S 40 // k stage stride (halfs) = 80 B
#define VST_S 56 // v stage stride (halfs) = 112 B
__global__ __launch_bounds__(256)
void spatial_attn_kernel(const __half* __restrict__ q, const __half* __restrict__ k,
                         const __half* __restrict__ v, __half* __restrict__ o)
{
    __shared__ float s_part[8][32][36];
    __shared__ float s_kvs[32][36];
    __shared__ float s_kss[32];
    __shared__ __align__(16) __half s_bv[48 * BVS];

    const int bt = blockIdx.x;
    const int h  = blockIdx.y;
    const int tid = threadIdx.x;
    const int w = tid >> 5, lane = tid & 31;

    const size_t baseBT = (size_t)bt * N_ * D_ + h * HD_;
    const int l0w = w * 256;

    char* wb = (char*)&s_part[w][0][0];
    __half* kst = (__half*)wb;
    __half* vst = (__half*)(wb + 16 * KST_S * 2);
    const uint32_t kstb = smem_u32(kst);
    const uint32_t vstb = smem_u32(vst);

    if (lane < 16) vst[lane * VST_S + 32] = __float2half(1.f);
    __syncwarp();

    const int fr_t = (lane & 7) + ((lane >> 4) & 1) * 8;
    const int fc_t = ((lane >> 3) & 1) * 16;

    float acc1[2][5][4];
    #pragma unroll
    for (int mt = 0; mt < 2; mt++)
        #pragma unroll
        for (int nt = 0; nt < 5; nt++)
            #pragma unroll
            for (int c = 0; c < 4; c++) acc1[mt][nt][c] = 0.f;

    const int crow = lane >> 2;
    const int cq4  = (lane & 3) * 8;

    uint4 kr2[2], vr2[2];
    auto ldgkv = [&](int c16) {
        int l0c = l0w + c16 * 16;
        #pragma unroll
        for (int i = 0; i < 2; i++) {
            int row = l0c + crow + i * 8;
            kr2[i] = *(const uint4*)(k + baseBT + (size_t)row * D_ + cq4);
            vr2[i] = *(const uint4*)(v + baseBT + (size_t)row * D_ + cq4);
        }
    };
    auto stskv = [&]() {
        #pragma unroll
        for (int i = 0; i < 2; i++) {
            int row = crow + i * 8;
            *(uint4*)(kst + row * KST_S + cq4) = kr2[i];
            *(uint4*)(vst + row * VST_S + cq4) = vr2[i];
        }
    };

    ldgkv(0); stskv(); __syncwarp();
    #pragma unroll 1
    for (int c16 = 0; c16 < 16; c16++) {
        if (c16 + 1 < 16) ldgkv(c16 + 1);

        uint32_t afr[2][4], bfr[3][4];
        ldm_x4_t(afr[0], kstb + fr_t * (KST_S * 2) + fc_t);
        ldm_x4_t(afr[1], kstb + fr_t * (KST_S * 2) + 32 + fc_t);
        ldm_x4_t(bfr[0], vstb + fr_t * (VST_S * 2) + fc_t);
        ldm_x4_t(bfr[1], vstb + fr_t * (VST_S * 2) + 32 + fc_t);
        ldm_x4_t(bfr[2], vstb + fr_t * (VST_S * 2) + 64 + fc_t);

        #pragma unroll
        for (int mt = 0; mt < 2; mt++)
            #pragma unroll
            for (int nt = 0; nt < 5; nt++) {
                int bn = nt >> 1, od = nt & 1;
                MMA_F16(acc1[mt][nt],
                        afr[mt][0], afr[mt][1], afr[mt][2], afr[mt][3],
                        bfr[bn][od], bfr[bn][od + 2]);
            }

        if (c16 + 1 < 16) {
            __syncwarp();
            stskv();
        }
        __syncwarp();
    }

    {
        const int r = lane >> 2;
        const int c2l = (lane & 3) << 1;
        #pragma unroll
        for (int mt = 0; mt < 2; mt++) {
            #pragma unroll
            for (int nt = 0; nt < 4; nt++) {
                *(float2*)&s_part[w][mt*16 + r][nt*8 + c2l] =
                    make_float2(acc1[mt][nt][0], acc1[mt][nt][1]);
                *(float2*)&s_part[w][mt*16 + r + 8][nt*8 + c2l] =
                    make_float2(acc1[mt][nt][2], acc1[mt][nt][3]);
            }
            if (c2l == 0) {
                s_part[w][mt*16 + r][32]     = acc1[mt][4][0];
                s_part[w][mt*16 + r + 8][32] = acc1[mt][4][2];
            }
        }
    }
    __syncthreads();

    {
        int m = tid >> 3, dd = (tid & 7) * 4;
        float4 s = make_float4(0.f, 0.f, 0.f, 0.f);
        #pragma unroll
        for (int wi = 0; wi < 8; wi++) {
            float4 p = *(const float4*)&s_part[wi][m][dd];
            s.x += p.x; s.y += p.y; s.z += p.z; s.w += p.w;
        }
        *(float4*)&s_kvs[m][dd] = s;
        if (tid < 32) {
            float s2 = 0.f;
            #pragma unroll
            for (int wi = 0; wi < 8; wi++) s2 += s_part[wi][tid][32];
            s_kss[tid] = s2;
        }
    }
    __syncthreads();

    for (int idx = tid; idx < 33 * 32; idx += 256) {
        int nn = idx >> 5, m = idx & 31;
        float val = (nn < 32) ? s_kvs[m][nn] : s_kss[m];
        s_bv[nn * BVS + m] = __float2half(val);
    }
    __syncthreads();

    const int fr = lane & 15;
    const int fc = (lane >> 4) * 16;
    const int r  = lane >> 2;
    const int c2 = (lane & 3) << 1;

    const uint32_t bvb = smem_u32(s_bv);
    uint32_t bf[3][2][4];
    #pragma unroll
    for (int bn = 0; bn < 3; bn++)
        #pragma unroll
        for (int s = 0; s < 2; s++)
            ldm_x4(bf[bn][s], bvb + (bn * 16 + fr) * (BVS * 2) + s * 32 + fc);

    __half* qs_h = (__half*)&s_part[w][0][0];
    const uint32_t qsb = smem_u32(qs_h);

    for (int c = 0; c < 8; c++) {
        const int l0 = l0w + c * 32;
        #pragma unroll
        for (int i2 = 0; i2 < 4; i2++) {
            int idx = lane + i2 * 32;
            int rr = idx >> 2, f = idx & 3;
            *(uint4*)(qs_h + rr * BVS + f * 8) =
                *(const uint4*)(q + baseBT + (size_t)(l0 + rr) * D_ + f * 8);
        }
        __syncwarp();

        uint32_t af[2][2][4];
        #pragma unroll
        for (int mt = 0; mt < 2; mt++)
            #pragma unroll
            for (int s = 0; s < 2; s++)
                ldm_x4(af[mt][s], qsb + (mt * 16 + fr) * (BVS * 2) + s * 32 + fc);

        float acc[2][5][4];
        #pragma unroll
        for (int mt = 0; mt < 2; mt++)
            #pragma unroll
            for (int nt = 0; nt < 5; nt++)
                #pragma unroll
                for (int cc = 0; cc < 4; cc++) acc[mt][nt][cc] = 0.f;

        #pragma unroll
        for (int mt = 0; mt < 2; mt++)
            #pragma unroll
            for (int nt = 0; nt < 5; nt++) {
                int bn = nt >> 1, od = nt & 1;
                #pragma unroll
                for (int s = 0; s < 2; s++)
                    MMA_F16(acc[mt][nt],
                            af[mt][s][0], af[mt][s][1], af[mt][s][2], af[mt][s][3],
                            bf[bn][s][od], bf[bn][s][od + 2]);
            }

        #pragma unroll
        for (int mt = 0; mt < 2; mt++) {
            float dlo = __shfl_sync(0xffffffffu, acc[mt][4][0], lane & 28);
            float dhi = __shfl_sync(0xffffffffu, acc[mt][4][2], lane & 28);
            float ilo = 1.f / fmaxf(dlo + (float)N_, 1e-5f);
            float ihi = 1.f / fmaxf(dhi + (float)N_, 1e-5f);
            int tlo = l0 + mt * 16 + r;
            int thi = tlo + 8;
            #pragma unroll
            for (int nt = 0; nt < 4; nt++) {
                int d = nt * 8 + c2;
                float2 vl = h2f2(*(const uint32_t*)(v + baseBT + (size_t)tlo * D_ + d));
                float2 vh = h2f2(*(const uint32_t*)(v + baseBT + (size_t)thi * D_ + d));
                float r0 = (acc[mt][nt][0] + (float)N_ * vl.x) * ilo;
                float r1 = (acc[mt][nt][1] + (float)N_ * vl.y) * ilo;
                float r2 = (acc[mt][nt][2] + (float)N_ * vh.x) * ihi;
                float r3 = (acc[mt][nt][3] + (float)N_ * vh.y) * ihi;
                *(uint32_t*)(o + baseBT + (size_t)tlo * D_ + d) = f2h2(r0, r1);
                *(uint32_t*)(o + baseBT + (size_t)thi * D_ + d) = f2h2(r2, r3);
            }
        }
        __syncwarp();
    }
}

// ---------------------------------------------------------------------------
// Temporal linear attention (attend over T=24). Block = (b, n), warp = head.
// Phase 1: swapped-operand mma (kvs^T = [v|1]^T k, token dim padded to 32).
// Phase 2: mma.
// ---------------------------------------------------------------------------
#define TKS 40
#define TVS 56
#define TPH 3200
#define TSM_BYTES (8 * TPH * 2)            // 51200
__global__ __launch_bounds__(256)
void temporal_attn_kernel(const __half* __restrict__ q, const __half* __restrict__ k,
                          const __half* __restrict__ v, __half* __restrict__ o)
{
    extern __shared__ __align__(16) __half smh[];
    const int bn = blockIdx.x;
    const int b = bn >> 11;
    const int n = bn & 2047;
    const int tid = threadIdx.x;
    const int h = tid >> 5, lane = tid & 31;

    __half* hb   = smh + h * TPH;
    __half* kst  = hb;
    __half* vst  = hb + 32 * TKS;
    __half* bv_h = hb;
    __half* qs_h = hb + 48 * BVS;

    const size_t base = ((size_t)b * T_ * N_ + n) * D_ + h * HD_;
    const size_t sT = (size_t)N_ * D_;

    const uint32_t kstb = smem_u32(kst);
    const uint32_t vstb = smem_u32(vst);

    {
        const uint4 z = make_uint4(0, 0, 0, 0);
        #pragma unroll
        for (int i = 0; i < 3; i++) {
            int idx = lane + i * 32;
            if (idx < 40) {
                int rr = idx / 5, cc = idx % 5;
                *(uint4*)(kst + (24 + rr) * TKS + cc * 8) = z;
            } else {
                int j = idx - 40;
                int rr = j / 7, cc = j % 7;
                *(uint4*)(vst + (24 + rr) * TVS + cc * 8) = z;
            }
        }
    }
    #pragma unroll
    for (int i = 0; i < 3; i++) {
        int idx = lane + i * 32;
        int t = idx >> 2, f = idx & 3;
        *(uint4*)(kst + t * TKS + f * 8) =
            *(const uint4*)(k + base + (size_t)t * sT + f * 8);
        *(uint4*)(vst + t * TVS + f * 8) =
            *(const uint4*)(v + base + (size_t)t * sT + f * 8);
    }
    if (lane < 24) vst[lane * TVS + 32] = __float2half(1.f);
    __syncwarp();

    const int fr_t = (lane & 7) + ((lane >> 4) & 1) * 8;
    const int fc_t = ((lane >> 3) & 1) * 16;

    float acc1[3][4][4];
    #pragma unroll
    for (int mi = 0; mi < 3; mi++)
        #pragma unroll
        for (int ni = 0; ni < 4; ni++)
            #pragma unroll
            for (int c = 0; c < 4; c++) acc1[mi][ni][c] = 0.f;

    #pragma unroll
    for (int s = 0; s < 2; s++) {
        uint32_t afr[3][4], bfr[2][4];
        #pragma unroll
        for (int mi = 0; mi < 3; mi++)
            ldm_x4_t(afr[mi], vstb + (s * 16 + fr_t) * (TVS * 2) + mi * 32 + fc_t);
        #pragma unroll
        for (int bi = 0; bi < 2; bi++)
            ldm_x4_t(bfr[bi], kstb + (s * 16 + fr_t) * (TKS * 2) + bi * 32 + fc_t);
        #pragma unroll
        for (int mi = 0; mi < 3; mi++)
            #pragma unroll
            for (int ni = 0; ni < 4; ni++) {
                int bi = ni >> 1, od = ni & 1;
                MMA_F16(acc1[mi][ni],
                        afr[mi][0], afr[mi][1], afr[mi][2], afr[mi][3],
                        bfr[bi][od], bfr[bi][od + 2]);
            }
    }
    __syncwarp();

    const int r  = lane >> 2;
    const int c2 = (lane & 3) << 1;

    #pragma unroll
    for (int mi = 0; mi < 3; mi++)
        #pragma unroll
        for (int ni = 0; ni < 4; ni++) {
            *(uint32_t*)(bv_h + (mi * 16 + r) * BVS + ni * 8 + c2) =
                f2h2(acc1[mi][ni][0], acc1[mi][ni][1]);
            *(uint32_t*)(bv_h + (mi * 16 + r + 8) * BVS + ni * 8 + c2) =
                f2h2(acc1[mi][ni][2], acc1[mi][ni][3]);
        }
    #pragma unroll
    for (int i = 0; i < 3; i++) {
        int idx = lane + i * 32;
        int t = idx >> 2, f = idx & 3;
        *(uint4*)(qs_h + t * BVS + f * 8) =
            *(const uint4*)(q + base + (size_t)t * sT + f * 8);
    }
    __syncwarp();

    const int fr = lane & 15;
    const int fc = (lane >> 4) * 16;

    const uint32_t bvb = smem_u32(bv_h);
    const uint32_t qsb = smem_u32(qs_h);

    uint32_t bf[3][2][4], af[2][2][4];
    #pragma unroll
    for (int bn2 = 0; bn2 < 3; bn2++)
        #pragma unroll
        for (int s = 0; s < 2; s++)
            ldm_x4(bf[bn2][s], bvb + (bn2 * 16 + fr) * (BVS * 2) + s * 32 + fc);
    #pragma unroll
    for (int mt = 0; mt < 2; mt++)
        #pragma unroll
        for (int s = 0; s < 2; s++)
            ldm_x4(af[mt][s], qsb + (mt * 16 + fr) * (BVS * 2) + s * 32 + fc);

    float acc[2][5][4];
    #pragma unroll
    for (int mt = 0; mt < 2; mt++)
        #pragma unroll
        for (int nt = 0; nt < 5; nt++)
            #pragma unroll
            for (int cc = 0; cc < 4; cc++) acc[mt][nt][cc] = 0.f;

    #pragma unroll
    for (int mt = 0; mt < 2; mt++)
        #pragma unroll
        for (int nt = 0; nt < 5; nt++) {
            int bn2 = nt >> 1, od = nt & 1;
            #pragma unroll
            for (int s = 0; s < 2; s++)
                MMA_F16(acc[mt][nt],
                        af[mt][s][0], af[mt][s][1], af[mt][s][2], af[mt][s][3],
                        bf[bn2][s][od], bf[bn2][s][od + 2]);
        }

    #pragma unroll
    for (int mt = 0; mt < 2; mt++) {
        float dlo = __shfl_sync(0xffffffffu, acc[mt][4][0], lane & 28);
        float dhi = __shfl_sync(0xffffffffu, acc[mt][4][2], lane & 28);
        float ilo = 1.f / fmaxf(dlo + (float)T_, 1e-5f);
        float ihi = 1.f / fmaxf(dhi + (float)T_, 1e-5f);
        int tlo = mt * 16 + r;
        int thi = tlo + 8;
        bool hiv = (thi < T_);
        #pragma unroll
        for (int nt = 0; nt < 4; nt++) {
            int d = nt * 8 + c2;
            float2 vl = h2f2(*(const uint32_t*)(v + base + (size_t)tlo * sT + d));
            float r0 = (acc[mt][nt][0] + (float)T_ * vl.x) * ilo;
            float r1 = (acc[mt][nt][1] + (float)T_ * vl.y) * ilo;
            *(uint32_t*)(o + base + (size_t)tlo * sT + d) = f2h2(r0, r1);
            if (hiv) {
                float2 vh = h2f2(*(const uint32_t*)(v + base + (size_t)thi * sT + d));
                float r2 = (acc[mt][nt][2] + (float)T_ * vh.x) * ihi;
                float r3 = (acc[mt][nt][3] + (float)T_ * vh.y) * ihi;
                *(uint32_t*)(o + base + (size_t)thi * sT + d) = f2h2(r2, r3);
            }
        }
    }
}

// ---------------------------------------------------------------------------
extern "C" void kernel_launch(void* const* d_in, const int* in_sizes, int n_in,
                              void* d_out, int out_size)
{
    const float* x     = (const float*)d_in[0];
    const float* w_qkv = (const float*)d_in[1];
    const float* w_out = (const float*)d_in[2];
    const float* b_out = (const float*)d_in[3];
    float* out = (float*)d_out;

    __half *q, *k, *v, *os, *ot, *wqh, *woh;
    cudaGetSymbolAddress((void**)&q,   g_q);
    cudaGetSymbolAddress((void**)&k,   g_k);
    cudaGetSymbolAddress((void**)&v,   g_v);
    cudaGetSymbolAddress((void**)&os,  g_os);
    cudaGetSymbolAddress((void**)&ot,  g_ot);
    cudaGetSymbolAddress((void**)&wqh, g_wqh);
    cudaGetSymbolAddress((void**)&woh, g_woh);

    cudaFuncSetAttribute(gemm_qkv_kernel,
                         cudaFuncAttributeMaxDynamicSharedMemorySize, G1_SMEM);
    cudaFuncSetAttribute(gemm_out_kernel,
                         cudaFuncAttributeMaxDynamicSharedMemorySize, G2_SMEM);
    cudaFuncSetAttribute(temporal_attn_kernel,
                         cudaFuncAttributeMaxDynamicSharedMemorySize, TSM_BYTES);

    // 0) convert weights to fp16 scratch
    {
        int total = (768 * 256 + 256 * 512) / 2;
        cvt_weights_kernel<<<(total + 255) / 256, 256>>>(w_qkv, w_out, wqh, woh);
    }
    // 1) QKV projection (fp16 mma, A-resident, 256-wide n-tiles) + fused l2norm
    gemm_qkv_kernel<<<MTOK / 128, 256, G1_SMEM>>>(x, wqh, q, k, v);

    // 2) spatial attention (both phases on tensor cores)
    {
        dim3 grid(B_ * T_, H_);
        spatial_attn_kernel<<<grid, 256>>>(q, k, v, os);
    }
    // 3) temporal attention (both phases on tensor cores)
    temporal_attn_kernel<<<B_ * N_, 256, TSM_BYTES>>>(q, k, v, ot);

    // 4) output projection + bias (fp16 mma, CTA 128x256 full-N)
    gemm_out_kernel<<<MTOK / 128, 256, G2_SMEM>>>(os, ot, woh, b_out, out);
}

// round 15
// speedup vs baseline: 1.1626x; 1.1626x over previous
#include <cuda_runtime.h>
#include <cuda_fp16.h>
#include <math.h>
#include <stdint.h>

#define B_  4
#define T_  24
#define N_  2048
#define D_  256
#define H_  8
#define HD_ 32
#define MTOK (B_*T_*N_)           // 196608 tokens
#define ELEMS ((size_t)MTOK * D_) // 50,331,648

// Scratch (device globals; allocation-free per harness rules). All fp16.
__device__ __half g_q [ELEMS];
__device__ __half g_k [ELEMS];
__device__ __half g_v [ELEMS];
__device__ __half g_os[ELEMS];
__device__ __half g_ot[ELEMS];
__device__ __half g_wqh[768*256];
__device__ __half g_woh[256*512];

// ---------------------------------------------------------------------------
// helpers
// ---------------------------------------------------------------------------
__device__ __forceinline__ uint32_t smem_u32(const void* p) {
    uint32_t a;
    asm("{ .reg .u64 t; cvta.to.shared.u64 t, %1; cvt.u32.u64 %0, t; }"
        : "=r"(a) : "l"(p));
    return a;
}
__device__ __forceinline__ uint32_t f2h2(float a, float b) {
    __half2 h = __floats2half2_rn(a, b);
    return *(uint32_t*)&h;
}
__device__ __forceinline__ uint2 f4h(float4 v) {
    return make_uint2(f2h2(v.x, v.y), f2h2(v.z, v.w));
}
__device__ __forceinline__ float2 h2f2(uint32_t h) {
    return __half22float2(*(__half2*)&h);
}
__device__ __forceinline__ void ldm_x4(uint32_t* r, uint32_t addr) {
    asm volatile("ldmatrix.sync.aligned.m8n8.x4.shared.b16 {%0,%1,%2,%3}, [%4];"
                 : "=r"(r[0]), "=r"(r[1]), "=r"(r[2]), "=r"(r[3]) : "r"(addr));
}
__device__ __forceinline__ void ldm_x4_t(uint32_t* r, uint32_t addr) {
    asm volatile("ldmatrix.sync.aligned.m8n8.x4.trans.shared.b16 {%0,%1,%2,%3}, [%4];"
                 : "=r"(r[0]), "=r"(r[1]), "=r"(r[2]), "=r"(r[3]) : "r"(addr));
}
#define MMA_F16(d, a0, a1, a2, a3, b0, b1)                                    \
    asm volatile("mma.sync.aligned.m16n8k16.row.col.f32.f16.f16.f32 "         \
                 "{%0,%1,%2,%3}, {%4,%5,%6,%7}, {%8,%9}, {%0,%1,%2,%3};"      \
                 : "+f"(d[0]), "+f"(d[1]), "+f"(d[2]), "+f"(d[3])             \
                 : "r"(a0), "r"(a1), "r"(a2), "r"(a3), "r"(b0), "r"(b1))

// ---- cp.async (L2 -> SMEM, 16B) ----
__device__ __forceinline__ void cp16(uint32_t saddr, const void* gaddr) {
    asm volatile("cp.async.cg.shared.global [%0], [%1], 16;"
                 :: "r"(saddr), "l"(gaddr) : "memory");
}
#define CP_COMMIT() asm volatile("cp.async.commit_group;" ::: "memory")
#define CP_WAIT0()  asm volatile("cp.async.wait_group 0;" ::: "memory")

// Row strides: 80B (chunk tiles) and 528B (resident A). Both ≡16 (mod 128).
#define CH_STRIDE 80
#define CH_BYTES  (128*CH_STRIDE)
#define AR_STRIDE 528
#define AR_BYTES  (128*AR_STRIDE)

// ---------------------------------------------------------------------------
// weight pre-conversion: f32 -> f16 (once per launch)
// ---------------------------------------------------------------------------
__global__ void cvt_weights_kernel(const float* __restrict__ wq,
                                   const float* __restrict__ wo,
                                   __half* __restrict__ wqh,
                                   __half* __restrict__ woh)
{
    int i = blockIdx.x * blockDim.x + threadIdx.x;
    const int NQ = 768 * 256 / 2;
    const int NO = 256 * 512 / 2;
    if (i < NQ) {
        float2 f = *(const float2*)(wq + i * 2);
        *(uint32_t*)(wqh + i * 2) = f2h2(f.x, f.y);
    } else if (i < NQ + NO) {
        int j = i - NQ;
        float2 f = *(const float2*)(wo + j * 2);
        *(uint32_t*)(woh + j * 2) = f2h2(f.x, f.y);
    }
}

// ===========================================================================
// GEMM1 (A-resident, fp16): qkv[M,768] = x[M,256] * w_qkv[768,256]^T
// Round-13 shape (warp tile 64x32, 2 CTA/SM); B loader via cp.async.
// ===========================================================================
#define G1_SMEM (AR_BYTES + 2*CH_BYTES)   // 88064

__global__ __launch_bounds__(256, 2)
void gemm_qkv_kernel(const float* __restrict__ A, const __half* __restrict__ Bw,
                     __half* __restrict__ outq, __half* __restrict__ outk,
                     __half* __restrict__ outv)
{
    extern __shared__ __align__(16) char smem[];
    const uint32_t sbase = smem_u32(smem);
    const int tid  = threadIdx.x;
    const int lane = tid & 31;
    const int wid  = tid >> 5;
    const int wm   = wid & 1;
    const int wn   = wid >> 1;
    const int m0   = blockIdx.x * 128;

    const int ar = tid >> 1;
    const int ac = tid & 1;
    const int fr = lane & 15;
    const int fc = (lane >> 4) * 16;
    const int r  = lane >> 2;
    const int c2 = (lane & 3) << 1;

    // ---- prologue: A (128x256 f32) -> resident fp16 smem, once ----
    #pragma unroll
    for (int j = 0; j < 8; j++) {
        const float* ap = A + (size_t)(m0 + ar) * 256 + (ac * 8 + j) * 16;
        uint2 h0 = f4h(*(const float4*)(ap + 0));
        uint2 h1 = f4h(*(const float4*)(ap + 4));
        uint2 h2 = f4h(*(const float4*)(ap + 8));
        uint2 h3 = f4h(*(const float4*)(ap + 12));
        char* dst = smem + ar * AR_STRIDE + (ac * 8 + j) * 32;
        *(uint4*)(dst)      = make_uint4(h0.x, h0.y, h1.x, h1.y);
        *(uint4*)(dst + 16) = make_uint4(h2.x, h2.y, h3.x, h3.y);
    }

    // ---- B loader: cp.async, 32 B per thread per chunk ----
    auto cpB = [&](int it, int buf) {
        const int nt = it >> 3, kt = it & 7;
        const __half* bp = Bw + (size_t)(nt * 128 + ar) * 256 + kt * 32 + ac * 16;
        uint32_t dst = sbase + AR_BYTES + buf * CH_BYTES + ar * CH_STRIDE + ac * 32;
        cp16(dst, bp);
        cp16(dst + 16, bp + 8);
        CP_COMMIT();
    };

    float acc[4][4][4];
    #pragma unroll
    for (int i = 0; i < 4; i++)
        #pragma unroll
        for (int j = 0; j < 4; j++)
            #pragma unroll
            for (int c = 0; c < 4; c++) acc[i][j][c] = 0.f;

    cpB(0, 0);
    CP_WAIT0();
    __syncthreads();

    #pragma unroll 1
    for (int it = 0; it < 48; it++) {
        if (it + 1 < 48) cpB(it + 1, (it + 1) & 1);

        {
            const int kt = it & 7;
            const uint32_t abase = sbase + kt * 64;
            const uint32_t bbase = sbase + AR_BYTES + (it & 1) * CH_BYTES;
            #pragma unroll
            for (int s = 0; s < 2; s++) {
                uint32_t af[4][4], bf[2][4];
                #pragma unroll
                for (int mt = 0; mt < 4; mt++) {
                    int row = wm * 64 + mt * 16 + fr;
                    ldm_x4(af[mt], abase + row * AR_STRIDE + s * 32 + fc);
                }
                #pragma unroll
                for (int bi = 0; bi < 2; bi++) {
                    int row = wn * 32 + bi * 16 + fr;
                    ldm_x4(bf[bi], bbase + row * CH_STRIDE + s * 32 + fc);
                }
                #pragma unroll
                for (int mt = 0; mt < 4; mt++)
                    #pragma unroll
                    for (int nt2 = 0; nt2 < 4; nt2++) {
                        int bi = nt2 >> 1, od = nt2 & 1;
                        MMA_F16(acc[mt][nt2],
                                af[mt][0], af[mt][1], af[mt][2], af[mt][3],
                                bf[bi][od], bf[bi][od + 2]);
                    }
            }
        }

        if ((it & 7) == 7) {
            const int n0g = (it >> 3) * 128;
            const int sel = n0g >> 8;

            if (sel < 2) {
                #pragma unroll
                for (int mt = 0; mt < 4; mt++) {
                    float sslo = 0.f, sshi = 0.f;
                    #pragma unroll
                    for (int nt2 = 0; nt2 < 4; nt2++) {
                        sslo = fmaf(acc[mt][nt2][0], acc[mt][nt2][0], sslo);
                        sslo = fmaf(acc[mt][nt2][1], acc[mt][nt2][1], sslo);
                        sshi = fmaf(acc[mt][nt2][2], acc[mt][nt2][2], sshi);
                        sshi = fmaf(acc[mt][nt2][3], acc[mt][nt2][3], sshi);
                    }
                    sslo += __shfl_xor_sync(0xffffffffu, sslo, 1);
                    sslo += __shfl_xor_sync(0xffffffffu, sslo, 2);
                    sshi += __shfl_xor_sync(0xffffffffu, sshi, 1);
                    sshi += __shfl_xor_sync(0xffffffffu, sshi, 2);
                    float slo = 1.f / fmaxf(sqrtf(sslo), 1e-12f);
                    float shi = 1.f / fmaxf(sqrtf(sshi), 1e-12f);
                    #pragma unroll
                    for (int nt2 = 0; nt2 < 4; nt2++) {
                        acc[mt][nt2][0] *= slo; acc[mt][nt2][1] *= slo;
                        acc[mt][nt2][2] *= shi; acc[mt][nt2][3] *= shi;
                    }
                }
            }

            __half* dst = (sel == 0) ? outq : ((sel == 1) ? outk : outv);
            #pragma unroll
            for (int mt = 0; mt < 4; mt++) {
                int m = m0 + wm * 64 + mt * 16 + r;
                #pragma unroll
                for (int nt2 = 0; nt2 < 4; nt2++) {
                    int col = ((n0g + wn * 32 + nt2 * 8 + c2) & 255);
                    float* a = acc[mt][nt2];
                    *(uint32_t*)(dst + (size_t)m * 256 + col)       = f2h2(a[0], a[1]);
                    *(uint32_t*)(dst + (size_t)(m + 8) * 256 + col) = f2h2(a[2], a[3]);
                    a[0] = a[1] = a[2] = a[3] = 0.f;
                }
            }
        }

        if (it + 1 < 48) CP_WAIT0();
        __syncthreads();
    }
}

// ===========================================================================
// GEMM2 (fp16 in / f32 out): out = [os|ot] * w_out^T + b
// Round-13 shape (128x128 tile, warp 64x32, 2 CTA/SM); cp.async loaders.
// ===========================================================================
#define G2_SMEM (4*CH_BYTES)   // 40960

__global__ __launch_bounds__(256, 2)
void gemm_out_kernel(const __half* __restrict__ A0, const __half* __restrict__ A1,
                     const __half* __restrict__ Bw,
                     const float* __restrict__ bias,
                     float* __restrict__ out)
{
    extern __shared__ __align__(16) char smem[];
    const uint32_t sbase = smem_u32(smem);
    const int tid  = threadIdx.x;
    const int lane = tid & 31;
    const int wid  = tid >> 5;
    const int wm   = wid & 1;
    const int wn   = wid >> 1;
    const int m0   = blockIdx.y * 128;
    const int n0g  = blockIdx.x * 128;

    const int ar = tid >> 1;
    const int ac = tid & 1;
    const int fr = lane & 15;
    const int fc = (lane >> 4) * 16;
    const int r  = lane >> 2;
    const int c2 = (lane & 3) << 1;

    auto cpAB = [&](int kt, int buf) {
        const int k0 = kt * 32;
        const __half* Asrc = (k0 < 256) ? A0 : A1;
        const int kc = k0 & 255;
        const __half* ap = Asrc + (size_t)(m0 + ar) * 256 + kc + ac * 16;
        uint32_t da = sbase + buf * 2 * CH_BYTES + ar * CH_STRIDE + ac * 32;
        cp16(da, ap);
        cp16(da + 16, ap + 8);
        const __half* bp = Bw + (size_t)(n0g + ar) * 512 + k0 + ac * 16;
        uint32_t db = da + CH_BYTES;
        cp16(db, bp);
        cp16(db + 16, bp + 8);
        CP_COMMIT();
    };

    float acc[4][4][4];
    #pragma unroll
    for (int i = 0; i < 4; i++)
        #pragma unroll
        for (int j = 0; j < 4; j++)
            #pragma unroll
            for (int c = 0; c < 4; c++) acc[i][j][c] = 0.f;

    cpAB(0, 0);
    CP_WAIT0();
    __syncthreads();

    #pragma unroll 1
    for (int kt = 0; kt < 16; kt++) {
        if (kt + 1 < 16) cpAB(kt + 1, (kt + 1) & 1);

        {
            const uint32_t abase = sbase + (kt & 1) * 2 * CH_BYTES;
            const uint32_t bbase = abase + CH_BYTES;
            #pragma unroll
            for (int s = 0; s < 2; s++) {
                uint32_t af[4][4], bf[2][4];
                #pragma unroll
                for (int mt = 0; mt < 4; mt++) {
                    int row = wm * 64 + mt * 16 + fr;
                    ldm_x4(af[mt], abase + row * CH_STRIDE + s * 32 + fc);
                }
                #pragma unroll
                for (int bi = 0; bi < 2; bi++) {
                    int row = wn * 32 + bi * 16 + fr;
                    ldm_x4(bf[bi], bbase + row * CH_STRIDE + s * 32 + fc);
                }
                #pragma unroll
                for (int mt = 0; mt < 4; mt++)
                    #pragma unroll
                    for (int nt2 = 0; nt2 < 4; nt2++) {
                        int bi = nt2 >> 1, od = nt2 & 1;
                        MMA_F16(acc[mt][nt2],
                                af[mt][0], af[mt][1], af[mt][2], af[mt][3],
                                bf[bi][od], bf[bi][od + 2]);
                    }
            }
        }

        if (kt + 1 < 16) CP_WAIT0();
        __syncthreads();
    }

    #pragma unroll
    for (int mt = 0; mt < 4; mt++) {
        int m = m0 + wm * 64 + mt * 16 + r;
        #pragma unroll
        for (int nt = 0; nt < 4; nt++) {
            int n = n0g + wn * 32 + nt * 8 + c2;
            float* a = acc[mt][nt];
            float b0 = bias[n], b1 = bias[n + 1];
            *(float2*)(out + (size_t)m * 256 + n)       = make_float2(a[0] + b0, a[1] + b1);
            *(float2*)(out + (size_t)(m + 8) * 256 + n) = make_float2(a[2] + b0, a[3] + b1);
        }
    }
}

// ---------------------------------------------------------------------------
// Spatial linear attention (attend over N=2048). Block = (bt, h), 8 warps.
// Phase 1: mma via ldmatrix.trans — kvs = k^T [v | 1], kss = column 32.
// Phase 2: mma with B = [kvs^T | kss].
// ---------------------------------------------------------------------------
#define BVS 40   // half stride (80 B) for phase-2 B / q staging rows
#define KST_S 40 // k stage stride (halfs) = 80 B
#define VST_S 56 // v stage stride (halfs) = 112 B
__global__ __launch_bounds__(256)
void spatial_attn_kernel(const __half* __restrict__ q, const __half* __restrict__ k,
                         const __half* __restrict__ v, __half* __restrict__ o)
{
    __shared__ float s_part[8][32][36];
    __shared__ float s_kvs[32][36];
    __shared__ float s_kss[32];
    __shared__ __align__(16) __half s_bv[48 * BVS];

    const int bt = blockIdx.x;
    const int h  = blockIdx.y;
    const int tid = threadIdx.x;
    const int w = tid >> 5, lane = tid & 31;

    const size_t baseBT = (size_t)bt * N_ * D_ + h * HD_;
    const int l0w = w * 256;

    char* wb = (char*)&s_part[w][0][0];
    __half* kst = (__half*)wb;
    __half* vst = (__half*)(wb + 16 * KST_S * 2);
    const uint32_t kstb = smem_u32(kst);
    const uint32_t vstb = smem_u32(vst);

    if (lane < 16) vst[lane * VST_S + 32] = __float2half(1.f);
    __syncwarp();

    const int fr_t = (lane & 7) + ((lane >> 4) & 1) * 8;
    const int fc_t = ((lane >> 3) & 1) * 16;

    float acc1[2][5][4];
    #pragma unroll
    for (int mt = 0; mt < 2; mt++)
        #pragma unroll
        for (int nt = 0; nt < 5; nt++)
            #pragma unroll
            for (int c = 0; c < 4; c++) acc1[mt][nt][c] = 0.f;

    const int crow = lane >> 2;
    const int cq4  = (lane & 3) * 8;

    uint4 kr2[2], vr2[2];
    auto ldgkv = [&](int c16) {
        int l0c = l0w + c16 * 16;
        #pragma unroll
        for (int i = 0; i < 2; i++) {
            int row = l0c + crow + i * 8;
            kr2[i] = *(const uint4*)(k + baseBT + (size_t)row * D_ + cq4);
            vr2[i] = *(const uint4*)(v + baseBT + (size_t)row * D_ + cq4);
        }
    };
    auto stskv = [&]() {
        #pragma unroll
        for (int i = 0; i < 2; i++) {
            int row = crow + i * 8;
            *(uint4*)(kst + row * KST_S + cq4) = kr2[i];
            *(uint4*)(vst + row * VST_S + cq4) = vr2[i];
        }
    };

    ldgkv(0); stskv(); __syncwarp();
    #pragma unroll 1
    for (int c16 = 0; c16 < 16; c16++) {
        if (c16 + 1 < 16) ldgkv(c16 + 1);

        uint32_t afr[2][4], bfr[3][4];
        ldm_x4_t(afr[0], kstb + fr_t * (KST_S * 2) + fc_t);
        ldm_x4_t(afr[1], kstb + fr_t * (KST_S * 2) + 32 + fc_t);
        ldm_x4_t(bfr[0], vstb + fr_t * (VST_S * 2) + fc_t);
        ldm_x4_t(bfr[1], vstb + fr_t * (VST_S * 2) + 32 + fc_t);
        ldm_x4_t(bfr[2], vstb + fr_t * (VST_S * 2) + 64 + fc_t);

        #pragma unroll
        for (int mt = 0; mt < 2; mt++)
            #pragma unroll
            for (int nt = 0; nt < 5; nt++) {
                int bn = nt >> 1, od = nt & 1;
                MMA_F16(acc1[mt][nt],
                        afr[mt][0], afr[mt][1], afr[mt][2], afr[mt][3],
                        bfr[bn][od], bfr[bn][od + 2]);
            }

        if (c16 + 1 < 16) {
            __syncwarp();
            stskv();
        }
        __syncwarp();
    }

    {
        const int r = lane >> 2;
        const int c2l = (lane & 3) << 1;
        #pragma unroll
        for (int mt = 0; mt < 2; mt++) {
            #pragma unroll
            for (int nt = 0; nt < 4; nt++) {
                *(float2*)&s_part[w][mt*16 + r][nt*8 + c2l] =
                    make_float2(acc1[mt][nt][0], acc1[mt][nt][1]);
                *(float2*)&s_part[w][mt*16 + r + 8][nt*8 + c2l] =
                    make_float2(acc1[mt][nt][2], acc1[mt][nt][3]);
            }
            if (c2l == 0) {
                s_part[w][mt*16 + r][32]     = acc1[mt][4][0];
                s_part[w][mt*16 + r + 8][32] = acc1[mt][4][2];
            }
        }
    }
    __syncthreads();

    {
        int m = tid >> 3, dd = (tid & 7) * 4;
        float4 s = make_float4(0.f, 0.f, 0.f, 0.f);
        #pragma unroll
        for (int wi = 0; wi < 8; wi++) {
            float4 p = *(const float4*)&s_part[wi][m][dd];
            s.x += p.x; s.y += p.y; s.z += p.z; s.w += p.w;
        }
        *(float4*)&s_kvs[m][dd] = s;
        if (tid < 32) {
            float s2 = 0.f;
            #pragma unroll
            for (int wi = 0; wi < 8; wi++) s2 += s_part[wi][tid][32];
            s_kss[tid] = s2;
        }
    }
    __syncthreads();

    for (int idx = tid; idx < 33 * 32; idx += 256) {
        int nn = idx >> 5, m = idx & 31;
        float val = (nn < 32) ? s_kvs[m][nn] : s_kss[m];
        s_bv[nn * BVS + m] = __float2half(val);
    }
    __syncthreads();

    const int fr = lane & 15;
    const int fc = (lane >> 4) * 16;
    const int r  = lane >> 2;
    const int c2 = (lane & 3) << 1;

    const uint32_t bvb = smem_u32(s_bv);
    uint32_t bf[3][2][4];
    #pragma unroll
    for (int bn = 0; bn < 3; bn++)
        #pragma unroll
        for (int s = 0; s < 2; s++)
            ldm_x4(bf[bn][s], bvb + (bn * 16 + fr) * (BVS * 2) + s * 32 + fc);

    __half* qs_h = (__half*)&s_part[w][0][0];
    const uint32_t qsb = smem_u32(qs_h);

    for (int c = 0; c < 8; c++) {
        const int l0 = l0w + c * 32;
        #pragma unroll
        for (int i2 = 0; i2 < 4; i2++) {
            int idx = lane + i2 * 32;
            int rr = idx >> 2, f = idx & 3;
            *(uint4*)(qs_h + rr * BVS + f * 8) =
                *(const uint4*)(q + baseBT + (size_t)(l0 + rr) * D_ + f * 8);
        }
        __syncwarp();

        uint32_t af[2][2][4];
        #pragma unroll
        for (int mt = 0; mt < 2; mt++)
            #pragma unroll
            for (int s = 0; s < 2; s++)
                ldm_x4(af[mt][s], qsb + (mt * 16 + fr) * (BVS * 2) + s * 32 + fc);

        float acc[2][5][4];
        #pragma unroll
        for (int mt = 0; mt < 2; mt++)
            #pragma unroll
            for (int nt = 0; nt < 5; nt++)
                #pragma unroll
                for (int cc = 0; cc < 4; cc++) acc[mt][nt][cc] = 0.f;

        #pragma unroll
        for (int mt = 0; mt < 2; mt++)
            #pragma unroll
            for (int nt = 0; nt < 5; nt++) {
                int bn = nt >> 1, od = nt & 1;
                #pragma unroll
                for (int s = 0; s < 2; s++)
                    MMA_F16(acc[mt][nt],
                            af[mt][s][0], af[mt][s][1], af[mt][s][2], af[mt][s][3],
                            bf[bn][s][od], bf[bn][s][od + 2]);
            }

        #pragma unroll
        for (int mt = 0; mt < 2; mt++) {
            float dlo = __shfl_sync(0xffffffffu, acc[mt][4][0], lane & 28);
            float dhi = __shfl_sync(0xffffffffu, acc[mt][4][2], lane & 28);
            float ilo = 1.f / fmaxf(dlo + (float)N_, 1e-5f);
            float ihi = 1.f / fmaxf(dhi + (float)N_, 1e-5f);
            int tlo = l0 + mt * 16 + r;
            int thi = tlo + 8;
            #pragma unroll
            for (int nt = 0; nt < 4; nt++) {
                int d = nt * 8 + c2;
                float2 vl = h2f2(*(const uint32_t*)(v + baseBT + (size_t)tlo * D_ + d));
                float2 vh = h2f2(*(const uint32_t*)(v + baseBT + (size_t)thi * D_ + d));
                float r0 = (acc[mt][nt][0] + (float)N_ * vl.x) * ilo;
                float r1 = (acc[mt][nt][1] + (float)N_ * vl.y) * ilo;
                float r2 = (acc[mt][nt][2] + (float)N_ * vh.x) * ihi;
                float r3 = (acc[mt][nt][3] + (float)N_ * vh.y) * ihi;
                *(uint32_t*)(o + baseBT + (size_t)tlo * D_ + d) = f2h2(r0, r1);
                *(uint32_t*)(o + baseBT + (size_t)thi * D_ + d) = f2h2(r2, r3);
            }
        }
        __syncwarp();
    }
}

// ---------------------------------------------------------------------------
// Temporal linear attention (attend over T=24). Block = (b, n), warp = head.
// Phase 1: swapped-operand mma (kvs^T = [v|1]^T k, token dim padded to 32).
// Phase 2: mma.
// ---------------------------------------------------------------------------
#define TKS 40
#define TVS 56
#define TPH 3200
#define TSM_BYTES (8 * TPH * 2)            // 51200
__global__ __launch_bounds__(256)
void temporal_attn_kernel(const __half* __restrict__ q, const __half* __restrict__ k,
                          const __half* __restrict__ v, __half* __restrict__ o)
{
    extern __shared__ __align__(16) __half smh[];
    const int bn = blockIdx.x;
    const int b = bn >> 11;
    const int n = bn & 2047;
    const int tid = threadIdx.x;
    const int h = tid >> 5, lane = tid & 31;

    __half* hb   = smh + h * TPH;
    __half* kst  = hb;
    __half* vst  = hb + 32 * TKS;
    __half* bv_h = hb;
    __half* qs_h = hb + 48 * BVS;

    const size_t base = ((size_t)b * T_ * N_ + n) * D_ + h * HD_;
    const size_t sT = (size_t)N_ * D_;

    const uint32_t kstb = smem_u32(kst);
    const uint32_t vstb = smem_u32(vst);

    {
        const uint4 z = make_uint4(0, 0, 0, 0);
        #pragma unroll
        for (int i = 0; i < 3; i++) {
            int idx = lane + i * 32;
            if (idx < 40) {
                int rr = idx / 5, cc = idx % 5;
                *(uint4*)(kst + (24 + rr) * TKS + cc * 8) = z;
            } else {
                int j = idx - 40;
                int rr = j / 7, cc = j % 7;
                *(uint4*)(vst + (24 + rr) * TVS + cc * 8) = z;
            }
        }
    }
    #pragma unroll
    for (int i = 0; i < 3; i++) {
        int idx = lane + i * 32;
        int t = idx >> 2, f = idx & 3;
        *(uint4*)(kst + t * TKS + f * 8) =
            *(const uint4*)(k + base + (size_t)t * sT + f * 8);
        *(uint4*)(vst + t * TVS + f * 8) =
            *(const uint4*)(v + base + (size_t)t * sT + f * 8);
    }
    if (lane < 24) vst[lane * TVS + 32] = __float2half(1.f);
    __syncwarp();

    const int fr_t = (lane & 7) + ((lane >> 4) & 1) * 8;
    const int fc_t = ((lane >> 3) & 1) * 16;

    float acc1[3][4][4];
    #pragma unroll
    for (int mi = 0; mi < 3; mi++)
        #pragma unroll
        for (int ni = 0; ni < 4; ni++)
            #pragma unroll
            for (int c = 0; c < 4; c++) acc1[mi][ni][c] = 0.f;

    #pragma unroll
    for (int s = 0; s < 2; s++) {
        uint32_t afr[3][4], bfr[2][4];
        #pragma unroll
        for (int mi = 0; mi < 3; mi++)
            ldm_x4_t(afr[mi], vstb + (s * 16 + fr_t) * (TVS * 2) + mi * 32 + fc_t);
        #pragma unroll
        for (int bi = 0; bi < 2; bi++)
            ldm_x4_t(bfr[bi], kstb + (s * 16 + fr_t) * (TKS * 2) + bi * 32 + fc_t);
        #pragma unroll
        for (int mi = 0; mi < 3; mi++)
            #pragma unroll
            for (int ni = 0; ni < 4; ni++) {
                int bi = ni >> 1, od = ni & 1;
                MMA_F16(acc1[mi][ni],
                        afr[mi][0], afr[mi][1], afr[mi][2], afr[mi][3],
                        bfr[bi][od], bfr[bi][od + 2]);
            }
    }
    __syncwarp();

    const int r  = lane >> 2;
    const int c2 = (lane & 3) << 1;

    #pragma unroll
    for (int mi = 0; mi < 3; mi++)
        #pragma unroll
        for (int ni = 0; ni < 4; ni++) {
            *(uint32_t*)(bv_h + (mi * 16 + r) * BVS + ni * 8 + c2) =
                f2h2(acc1[mi][ni][0], acc1[mi][ni][1]);
            *(uint32_t*)(bv_h + (mi * 16 + r + 8) * BVS + ni * 8 + c2) =
                f2h2(acc1[mi][ni][2], acc1[mi][ni][3]);
        }
    #pragma unroll
    for (int i = 0; i < 3; i++) {
        int idx = lane + i * 32;
        int t = idx >> 2, f = idx & 3;
        *(uint4*)(qs_h + t * BVS + f * 8) =
            *(const uint4*)(q + base + (size_t)t * sT + f * 8);
    }
    __syncwarp();

    const int fr = lane & 15;
    const int fc = (lane >> 4) * 16;

    const uint32_t bvb = smem_u32(bv_h);
    const uint32_t qsb = smem_u32(qs_h);

    uint32_t bf[3][2][4], af[2][2][4];
    #pragma unroll
    for (int bn2 = 0; bn2 < 3; bn2++)
        #pragma unroll
        for (int s = 0; s < 2; s++)
            ldm_x4(bf[bn2][s], bvb + (bn2 * 16 + fr) * (BVS * 2) + s * 32 + fc);
    #pragma unroll
    for (int mt = 0; mt < 2; mt++)
        #pragma unroll
        for (int s = 0; s < 2; s++)
            ldm_x4(af[mt][s], qsb + (mt * 16 + fr) * (BVS * 2) + s * 32 + fc);

    float acc[2][5][4];
    #pragma unroll
    for (int mt = 0; mt < 2; mt++)
        #pragma unroll
        for (int nt = 0; nt < 5; nt++)
            #pragma unroll
            for (int cc = 0; cc < 4; cc++) acc[mt][nt][cc] = 0.f;

    #pragma unroll
    for (int mt = 0; mt < 2; mt++)
        #pragma unroll
        for (int nt = 0; nt < 5; nt++) {
            int bn2 = nt >> 1, od = nt & 1;
            #pragma unroll
            for (int s = 0; s < 2; s++)
                MMA_F16(acc[mt][nt],
                        af[mt][s][0], af[mt][s][1], af[mt][s][2], af[mt][s][3],
                        bf[bn2][s][od], bf[bn2][s][od + 2]);
        }

    #pragma unroll
    for (int mt = 0; mt < 2; mt++) {
        float dlo = __shfl_sync(0xffffffffu, acc[mt][4][0], lane & 28);
        float dhi = __shfl_sync(0xffffffffu, acc[mt][4][2], lane & 28);
        float ilo = 1.f / fmaxf(dlo + (float)T_, 1e-5f);
        float ihi = 1.f / fmaxf(dhi + (float)T_, 1e-5f);
        int tlo = mt * 16 + r;
        int thi = tlo + 8;
        bool hiv = (thi < T_);
        #pragma unroll
        for (int nt = 0; nt < 4; nt++) {
            int d = nt * 8 + c2;
            float2 vl = h2f2(*(const uint32_t*)(v + base + (size_t)tlo * sT + d));
            float r0 = (acc[mt][nt][0] + (float)T_ * vl.x) * ilo;
            float r1 = (acc[mt][nt][1] + (float)T_ * vl.y) * ilo;
            *(uint32_t*)(o + base + (size_t)tlo * sT + d) = f2h2(r0, r1);
            if (hiv) {
                float2 vh = h2f2(*(const uint32_t*)(v + base + (size_t)thi * sT + d));
                float r2 = (acc[mt][nt][2] + (float)T_ * vh.x) * ihi;
                float r3 = (acc[mt][nt][3] + (float)T_ * vh.y) * ihi;
                *(uint32_t*)(o + base + (size_t)thi * sT + d) = f2h2(r2, r3);
            }
        }
    }
}

// ---------------------------------------------------------------------------
extern "C" void kernel_launch(void* const* d_in, const int* in_sizes, int n_in,
                              void* d_out, int out_size)
{
    const float* x     = (const float*)d_in[0];
    const float* w_qkv = (const float*)d_in[1];
    const float* w_out = (const float*)d_in[2];
    const float* b_out = (const float*)d_in[3];
    float* out = (float*)d_out;

    __half *q, *k, *v, *os, *ot, *wqh, *woh;
    cudaGetSymbolAddress((void**)&q,   g_q);
    cudaGetSymbolAddress((void**)&k,   g_k);
    cudaGetSymbolAddress((void**)&v,   g_v);
    cudaGetSymbolAddress((void**)&os,  g_os);
    cudaGetSymbolAddress((void**)&ot,  g_ot);
    cudaGetSymbolAddress((void**)&wqh, g_wqh);
    cudaGetSymbolAddress((void**)&woh, g_woh);

    cudaFuncSetAttribute(gemm_qkv_kernel,
                         cudaFuncAttributeMaxDynamicSharedMemorySize, G1_SMEM);
    cudaFuncSetAttribute(gemm_out_kernel,
                         cudaFuncAttributeMaxDynamicSharedMemorySize, G2_SMEM);
    cudaFuncSetAttribute(temporal_attn_kernel,
                         cudaFuncAttributeMaxDynamicSharedMemorySize, TSM_BYTES);

    // 0) convert weights to fp16 scratch
    {
        int total = (768 * 256 + 256 * 512) / 2;
        cvt_weights_kernel<<<(total + 255) / 256, 256>>>(w_qkv, w_out, wqh, woh);
    }
    // 1) QKV projection (fp16 mma, A-resident, cp.async B loader) + fused l2norm
    gemm_qkv_kernel<<<MTOK / 128, 256, G1_SMEM>>>(x, wqh, q, k, v);

    // 2) spatial attention (both phases on tensor cores)
    {
        dim3 grid(B_ * T_, H_);
        spatial_attn_kernel<<<grid, 256>>>(q, k, v, os);
    }
    // 3) temporal attention (both phases on tensor cores)
    temporal_attn_kernel<<<B_ * N_, 256, TSM_BYTES>>>(q, k, v, ot);

    // 4) output projection + bias (fp16 mma, cp.async loaders)
    {
        dim3 grid(2, MTOK / 128);
        gemm_out_kernel<<<grid, 256, G2_SMEM>>>(os, ot, woh, b_out, out);
    }
}

// round 16
// speedup vs baseline: 1.2231x; 1.0521x over previous
#include <cuda_runtime.h>
#include <cuda_fp16.h>
#include <math.h>
#include <stdint.h>

#define B_  4
#define T_  24
#define N_  2048
#define D_  256
#define H_  8
#define HD_ 32
#define MTOK (B_*T_*N_)           // 196608 tokens
#define ELEMS ((size_t)MTOK * D_) // 50,331,648

// Scratch (device globals). Head-major layout: [h][token][32] halfs.
__device__ __half g_q [ELEMS];
__device__ __half g_k [ELEMS];
__device__ __half g_v [ELEMS];
__device__ __half g_os[ELEMS];
__device__ __half g_ot[ELEMS];
__device__ __half g_wqh[768*256];
__device__ __half g_woh[256*512];

// ---------------------------------------------------------------------------
// helpers
// ---------------------------------------------------------------------------
__device__ __forceinline__ uint32_t smem_u32(const void* p) {
    uint32_t a;
    asm("{ .reg .u64 t; cvta.to.shared.u64 t, %1; cvt.u32.u64 %0, t; }"
        : "=r"(a) : "l"(p));
    return a;
}
__device__ __forceinline__ uint32_t f2h2(float a, float b) {
    __half2 h = __floats2half2_rn(a, b);
    return *(uint32_t*)&h;
}
__device__ __forceinline__ uint2 f4h(float4 v) {
    return make_uint2(f2h2(v.x, v.y), f2h2(v.z, v.w));
}
__device__ __forceinline__ float2 h2f2(uint32_t h) {
    return __half22float2(*(__half2*)&h);
}
__device__ __forceinline__ void ldm_x4(uint32_t* r, uint32_t addr) {
    asm volatile("ldmatrix.sync.aligned.m8n8.x4.shared.b16 {%0,%1,%2,%3}, [%4];"
                 : "=r"(r[0]), "=r"(r[1]), "=r"(r[2]), "=r"(r[3]) : "r"(addr));
}
__device__ __forceinline__ void ldm_x4_t(uint32_t* r, uint32_t addr) {
    asm volatile("ldmatrix.sync.aligned.m8n8.x4.trans.shared.b16 {%0,%1,%2,%3}, [%4];"
                 : "=r"(r[0]), "=r"(r[1]), "=r"(r[2]), "=r"(r[3]) : "r"(addr));
}
#define MMA_F16(d, a0, a1, a2, a3, b0, b1)                                    \
    asm volatile("mma.sync.aligned.m16n8k16.row.col.f32.f16.f16.f32 "         \
                 "{%0,%1,%2,%3}, {%4,%5,%6,%7}, {%8,%9}, {%0,%1,%2,%3};"      \
                 : "+f"(d[0]), "+f"(d[1]), "+f"(d[2]), "+f"(d[3])             \
                 : "r"(a0), "r"(a1), "r"(a2), "r"(a3), "r"(b0), "r"(b1))

// ---- cp.async (L2 -> SMEM, 16B) ----
__device__ __forceinline__ void cp16(uint32_t saddr, const void* gaddr) {
    asm volatile("cp.async.cg.shared.global [%0], [%1], 16;"
                 :: "r"(saddr), "l"(gaddr) : "memory");
}
#define CP_COMMIT() asm volatile("cp.async.commit_group;" ::: "memory")
#define CP_WAIT0()  asm volatile("cp.async.wait_group 0;" ::: "memory")

// Row strides: 80B (chunk tiles) and 528B (resident A). Both ≡16 (mod 128).
#define CH_STRIDE 80
#define CH_BYTES  (128*CH_STRIDE)
#define AR_STRIDE 528
#define AR_BYTES  (128*AR_STRIDE)

// ---------------------------------------------------------------------------
// weight pre-conversion: f32 -> f16 (once per launch)
// ---------------------------------------------------------------------------
__global__ void cvt_weights_kernel(const float* __restrict__ wq,
                                   const float* __restrict__ wo,
                                   __half* __restrict__ wqh,
                                   __half* __restrict__ woh)
{
    int i = blockIdx.x * blockDim.x + threadIdx.x;
    const int NQ = 768 * 256 / 2;
    const int NO = 256 * 512 / 2;
    if (i < NQ) {
        float2 f = *(const float2*)(wq + i * 2);
        *(uint32_t*)(wqh + i * 2) = f2h2(f.x, f.y);
    } else if (i < NQ + NO) {
        int j = i - NQ;
        float2 f = *(const float2*)(wo + j * 2);
        *(uint32_t*)(woh + j * 2) = f2h2(f.x, f.y);
    }
}

// ===========================================================================
// GEMM1 (A-resident, fp16): qkv[M,768] = x[M,256] * w_qkv[768,256]^T
// Outputs written head-major: dst[h][m][32].
// ===========================================================================
#define G1_SMEM (AR_BYTES + 2*CH_BYTES)   // 88064

__global__ __launch_bounds__(256, 2)
void gemm_qkv_kernel(const float* __restrict__ A, const __half* __restrict__ Bw,
                     __half* __restrict__ outq, __half* __restrict__ outk,
                     __half* __restrict__ outv)
{
    extern __shared__ __align__(16) char smem[];
    const uint32_t sbase = smem_u32(smem);
    const int tid  = threadIdx.x;
    const int lane = tid & 31;
    const int wid  = tid >> 5;
    const int wm   = wid & 1;
    const int wn   = wid >> 1;
    const int m0   = blockIdx.x * 128;

    const int ar = tid >> 1;
    const int ac = tid & 1;
    const int fr = lane & 15;
    const int fc = (lane >> 4) * 16;
    const int r  = lane >> 2;
    const int c2 = (lane & 3) << 1;

    // ---- prologue: A (128x256 f32) -> resident fp16 smem, once ----
    #pragma unroll
    for (int j = 0; j < 8; j++) {
        const float* ap = A + (size_t)(m0 + ar) * 256 + (ac * 8 + j) * 16;
        uint2 h0 = f4h(*(const float4*)(ap + 0));
        uint2 h1 = f4h(*(const float4*)(ap + 4));
        uint2 h2 = f4h(*(const float4*)(ap + 8));
        uint2 h3 = f4h(*(const float4*)(ap + 12));
        char* dst = smem + ar * AR_STRIDE + (ac * 8 + j) * 32;
        *(uint4*)(dst)      = make_uint4(h0.x, h0.y, h1.x, h1.y);
        *(uint4*)(dst + 16) = make_uint4(h2.x, h2.y, h3.x, h3.y);
    }

    auto cpB = [&](int it, int buf) {
        const int nt = it >> 3, kt = it & 7;
        const __half* bp = Bw + (size_t)(nt * 128 + ar) * 256 + kt * 32 + ac * 16;
        uint32_t dst = sbase + AR_BYTES + buf * CH_BYTES + ar * CH_STRIDE + ac * 32;
        cp16(dst, bp);
        cp16(dst + 16, bp + 8);
        CP_COMMIT();
    };

    float acc[4][4][4];
    #pragma unroll
    for (int i = 0; i < 4; i++)
        #pragma unroll
        for (int j = 0; j < 4; j++)
            #pragma unroll
            for (int c = 0; c < 4; c++) acc[i][j][c] = 0.f;

    cpB(0, 0);
    CP_WAIT0();
    __syncthreads();

    #pragma unroll 1
    for (int it = 0; it < 48; it++) {
        if (it + 1 < 48) cpB(it + 1, (it + 1) & 1);

        {
            const int kt = it & 7;
            const uint32_t abase = sbase + kt * 64;
            const uint32_t bbase = sbase + AR_BYTES + (it & 1) * CH_BYTES;
            #pragma unroll
            for (int s = 0; s < 2; s++) {
                uint32_t af[4][4], bf[2][4];
                #pragma unroll
                for (int mt = 0; mt < 4; mt++) {
                    int row = wm * 64 + mt * 16 + fr;
                    ldm_x4(af[mt], abase + row * AR_STRIDE + s * 32 + fc);
                }
                #pragma unroll
                for (int bi = 0; bi < 2; bi++) {
                    int row = wn * 32 + bi * 16 + fr;
                    ldm_x4(bf[bi], bbase + row * CH_STRIDE + s * 32 + fc);
                }
                #pragma unroll
                for (int mt = 0; mt < 4; mt++)
                    #pragma unroll
                    for (int nt2 = 0; nt2 < 4; nt2++) {
                        int bi = nt2 >> 1, od = nt2 & 1;
                        MMA_F16(acc[mt][nt2],
                                af[mt][0], af[mt][1], af[mt][2], af[mt][3],
                                bf[bi][od], bf[bi][od + 2]);
                    }
            }
        }

        if ((it & 7) == 7) {
            const int tile = it >> 3;           // 0..5
            const int sel  = tile >> 1;         // 0=q,1=k,2=v
            const int hh   = wn + 4 * (tile & 1);  // head for this warp

            if (sel < 2) {   // q or k: warp's 32 n-cols = one head chunk
                #pragma unroll
                for (int mt = 0; mt < 4; mt++) {
                    float sslo = 0.f, sshi = 0.f;
                    #pragma unroll
                    for (int nt2 = 0; nt2 < 4; nt2++) {
                        sslo = fmaf(acc[mt][nt2][0], acc[mt][nt2][0], sslo);
                        sslo = fmaf(acc[mt][nt2][1], acc[mt][nt2][1], sslo);
                        sshi = fmaf(acc[mt][nt2][2], acc[mt][nt2][2], sshi);
                        sshi = fmaf(acc[mt][nt2][3], acc[mt][nt2][3], sshi);
                    }
                    sslo += __shfl_xor_sync(0xffffffffu, sslo, 1);
                    sslo += __shfl_xor_sync(0xffffffffu, sslo, 2);
                    sshi += __shfl_xor_sync(0xffffffffu, sshi, 1);
                    sshi += __shfl_xor_sync(0xffffffffu, sshi, 2);
                    float slo = 1.f / fmaxf(sqrtf(sslo), 1e-12f);
                    float shi = 1.f / fmaxf(sqrtf(sshi), 1e-12f);
                    #pragma unroll
                    for (int nt2 = 0; nt2 < 4; nt2++) {
                        acc[mt][nt2][0] *= slo; acc[mt][nt2][1] *= slo;
                        acc[mt][nt2][2] *= shi; acc[mt][nt2][3] *= shi;
                    }
                }
            }

            __half* dstb = (sel == 0) ? outq : ((sel == 1) ? outk : outv);
            __half* dsth = dstb + (size_t)hh * MTOK * HD_;
            #pragma unroll
            for (int mt = 0; mt < 4; mt++) {
                int m = m0 + wm * 64 + mt * 16 + r;
                #pragma unroll
                for (int nt2 = 0; nt2 < 4; nt2++) {
                    int cc = nt2 * 8 + c2;
                    float* a = acc[mt][nt2];
                    *(uint32_t*)(dsth + (size_t)m * HD_ + cc)       = f2h2(a[0], a[1]);
                    *(uint32_t*)(dsth + (size_t)(m + 8) * HD_ + cc) = f2h2(a[2], a[3]);
                    a[0] = a[1] = a[2] = a[3] = 0.f;
                }
            }
        }

        if (it + 1 < 48) CP_WAIT0();
        __syncthreads();
    }
}

// ===========================================================================
// GEMM2 (fp16 in / f32 out): out = [os|ot] * w_out^T + b
// A operands (os, ot) are head-major: each K-chunk = one head, contiguous.
// ===========================================================================
#define G2_SMEM (4*CH_BYTES)   // 40960

__global__ __launch_bounds__(256, 2)
void gemm_out_kernel(const __half* __restrict__ A0, const __half* __restrict__ A1,
                     const __half* __restrict__ Bw,
                     const float* __restrict__ bias,
                     float* __restrict__ out)
{
    extern __shared__ __align__(16) char smem[];
    const uint32_t sbase = smem_u32(smem);
    const int tid  = threadIdx.x;
    const int lane = tid & 31;
    const int wid  = tid >> 5;
    const int wm   = wid & 1;
    const int wn   = wid >> 1;
    const int m0   = blockIdx.y * 128;
    const int n0g  = blockIdx.x * 128;

    const int ar = tid >> 1;
    const int ac = tid & 1;
    const int fr = lane & 15;
    const int fc = (lane >> 4) * 16;
    const int r  = lane >> 2;
    const int c2 = (lane & 3) << 1;

    auto cpAB = [&](int kt, int buf) {
        const int k0 = kt * 32;
        const __half* Asrc = (k0 < 256) ? A0 : A1;
        const int hh = kt & 7;
        const __half* ap = Asrc + ((size_t)hh * MTOK + m0 + ar) * HD_ + ac * 16;
        uint32_t da = sbase + buf * 2 * CH_BYTES + ar * CH_STRIDE + ac * 32;
        cp16(da, ap);
        cp16(da + 16, ap + 8);
        const __half* bp = Bw + (size_t)(n0g + ar) * 512 + k0 + ac * 16;
        uint32_t db = da + CH_BYTES;
        cp16(db, bp);
        cp16(db + 16, bp + 8);
        CP_COMMIT();
    };

    float acc[4][4][4];
    #pragma unroll
    for (int i = 0; i < 4; i++)
        #pragma unroll
        for (int j = 0; j < 4; j++)
            #pragma unroll
            for (int c = 0; c < 4; c++) acc[i][j][c] = 0.f;

    cpAB(0, 0);
    CP_WAIT0();
    __syncthreads();

    #pragma unroll 1
    for (int kt = 0; kt < 16; kt++) {
        if (kt + 1 < 16) cpAB(kt + 1, (kt + 1) & 1);

        {
            const uint32_t abase = sbase + (kt & 1) * 2 * CH_BYTES;
            const uint32_t bbase = abase + CH_BYTES;
            #pragma unroll
            for (int s = 0; s < 2; s++) {
                uint32_t af[4][4], bf[2][4];
                #pragma unroll
                for (int mt = 0; mt < 4; mt++) {
                    int row = wm * 64 + mt * 16 + fr;
                    ldm_x4(af[mt], abase + row * CH_STRIDE + s * 32 + fc);
                }
                #pragma unroll
                for (int bi = 0; bi < 2; bi++) {
                    int row = wn * 32 + bi * 16 + fr;
                    ldm_x4(bf[bi], bbase + row * CH_STRIDE + s * 32 + fc);
                }
                #pragma unroll
                for (int mt = 0; mt < 4; mt++)
                    #pragma unroll
                    for (int nt2 = 0; nt2 < 4; nt2++) {
                        int bi = nt2 >> 1, od = nt2 & 1;
                        MMA_F16(acc[mt][nt2],
                                af[mt][0], af[mt][1], af[mt][2], af[mt][3],
                                bf[bi][od], bf[bi][od + 2]);
                    }
            }
        }

        if (kt + 1 < 16) CP_WAIT0();
        __syncthreads();
    }

    #pragma unroll
    for (int mt = 0; mt < 4; mt++) {
        int m = m0 + wm * 64 + mt * 16 + r;
        #pragma unroll
        for (int nt = 0; nt < 4; nt++) {
            int n = n0g + wn * 32 + nt * 8 + c2;
            float* a = acc[mt][nt];
            float b0 = bias[n], b1 = bias[n + 1];
            *(float2*)(out + (size_t)m * 256 + n)       = make_float2(a[0] + b0, a[1] + b1);
            *(float2*)(out + (size_t)(m + 8) * 256 + n) = make_float2(a[2] + b0, a[3] + b1);
        }
    }
}

// ---------------------------------------------------------------------------
// Spatial linear attention (attend over N=2048). Block = (bt, h), 8 warps.
// Head-major inputs: all loads/stores fully contiguous (rows 64 B apart).
// ---------------------------------------------------------------------------
#define BVS 40
#define KST_S 40
#define VST_S 56
__global__ __launch_bounds__(256)
void spatial_attn_kernel(const __half* __restrict__ q, const __half* __restrict__ k,
                         const __half* __restrict__ v, __half* __restrict__ o)
{
    __shared__ float s_part[8][32][36];
    __shared__ float s_kvs[32][36];
    __shared__ float s_kss[32];
    __shared__ __align__(16) __half s_bv[48 * BVS];

    const int bt = blockIdx.x;
    const int h  = blockIdx.y;
    const int tid = threadIdx.x;
    const int w = tid >> 5, lane = tid & 31;

    const size_t baseBT = ((size_t)h * (B_ * T_) + bt) * N_ * HD_;
    const int l0w = w * 256;

    char* wb = (char*)&s_part[w][0][0];
    __half* kst = (__half*)wb;
    __half* vst = (__half*)(wb + 16 * KST_S * 2);
    const uint32_t kstb = smem_u32(kst);
    const uint32_t vstb = smem_u32(vst);

    if (lane < 16) vst[lane * VST_S + 32] = __float2half(1.f);
    __syncwarp();

    const int fr_t = (lane & 7) + ((lane >> 4) & 1) * 8;
    const int fc_t = ((lane >> 3) & 1) * 16;

    float acc1[2][5][4];
    #pragma unroll
    for (int mt = 0; mt < 2; mt++)
        #pragma unroll
        for (int nt = 0; nt < 5; nt++)
            #pragma unroll
            for (int c = 0; c < 4; c++) acc1[mt][nt][c] = 0.f;

    const int crow = lane >> 2;
    const int cq4  = (lane & 3) * 8;

    uint4 kr2[2], vr2[2];
    auto ldgkv = [&](int c16) {
        int l0c = l0w + c16 * 16;
        #pragma unroll
        for (int i = 0; i < 2; i++) {
            int row = l0c + crow + i * 8;
            kr2[i] = *(const uint4*)(k + baseBT + (size_t)row * HD_ + cq4);
            vr2[i] = *(const uint4*)(v + baseBT + (size_t)row * HD_ + cq4);
        }
    };
    auto stskv = [&]() {
        #pragma unroll
        for (int i = 0; i < 2; i++) {
            int row = crow + i * 8;
            *(uint4*)(kst + row * KST_S + cq4) = kr2[i];
            *(uint4*)(vst + row * VST_S + cq4) = vr2[i];
        }
    };

    ldgkv(0); stskv(); __syncwarp();
    #pragma unroll 1
    for (int c16 = 0; c16 < 16; c16++) {
        if (c16 + 1 < 16) ldgkv(c16 + 1);

        uint32_t afr[2][4], bfr[3][4];
        ldm_x4_t(afr[0], kstb + fr_t * (KST_S * 2) + fc_t);
        ldm_x4_t(afr[1], kstb + fr_t * (KST_S * 2) + 32 + fc_t);
        ldm_x4_t(bfr[0], vstb + fr_t * (VST_S * 2) + fc_t);
        ldm_x4_t(bfr[1], vstb + fr_t * (VST_S * 2) + 32 + fc_t);
        ldm_x4_t(bfr[2], vstb + fr_t * (VST_S * 2) + 64 + fc_t);

        #pragma unroll
        for (int mt = 0; mt < 2; mt++)
            #pragma unroll
            for (int nt = 0; nt < 5; nt++) {
                int bn = nt >> 1, od = nt & 1;
                MMA_F16(acc1[mt][nt],
                        afr[mt][0], afr[mt][1], afr[mt][2], afr[mt][3],
                        bfr[bn][od], bfr[bn][od + 2]);
            }

        if (c16 + 1 < 16) {
            __syncwarp();
            stskv();
        }
        __syncwarp();
    }

    {
        const int r = lane >> 2;
        const int c2l = (lane & 3) << 1;
        #pragma unroll
        for (int mt = 0; mt < 2; mt++) {
            #pragma unroll
            for (int nt = 0; nt < 4; nt++) {
                *(float2*)&s_part[w][mt*16 + r][nt*8 + c2l] =
                    make_float2(acc1[mt][nt][0], acc1[mt][nt][1]);
                *(float2*)&s_part[w][mt*16 + r + 8][nt*8 + c2l] =
                    make_float2(acc1[mt][nt][2], acc1[mt][nt][3]);
            }
            if (c2l == 0) {
                s_part[w][mt*16 + r][32]     = acc1[mt][4][0];
                s_part[w][mt*16 + r + 8][32] = acc1[mt][4][2];
            }
        }
    }
    __syncthreads();

    {
        int m = tid >> 3, dd = (tid & 7) * 4;
        float4 s = make_float4(0.f, 0.f, 0.f, 0.f);
        #pragma unroll
        for (int wi = 0; wi < 8; wi++) {
            float4 p = *(const float4*)&s_part[wi][m][dd];
            s.x += p.x; s.y += p.y; s.z += p.z; s.w += p.w;
        }
        *(float4*)&s_kvs[m][dd] = s;
        if (tid < 32) {
            float s2 = 0.f;
            #pragma unroll
            for (int wi = 0; wi < 8; wi++) s2 += s_part[wi][tid][32];
            s_kss[tid] = s2;
        }
    }
    __syncthreads();

    for (int idx = tid; idx < 33 * 32; idx += 256) {
        int nn = idx >> 5, m = idx & 31;
        float val = (nn < 32) ? s_kvs[m][nn] : s_kss[m];
        s_bv[nn * BVS + m] = __float2half(val);
    }
    __syncthreads();

    const int fr = lane & 15;
    const int fc = (lane >> 4) * 16;
    const int r  = lane >> 2;
    const int c2 = (lane & 3) << 1;

    const uint32_t bvb = smem_u32(s_bv);
    uint32_t bf[3][2][4];
    #pragma unroll
    for (int bn = 0; bn < 3; bn++)
        #pragma unroll
        for (int s = 0; s < 2; s++)
            ldm_x4(bf[bn][s], bvb + (bn * 16 + fr) * (BVS * 2) + s * 32 + fc);

    __half* qs_h = (__half*)&s_part[w][0][0];
    const uint32_t qsb = smem_u32(qs_h);

    for (int c = 0; c < 8; c++) {
        const int l0 = l0w + c * 32;
        #pragma unroll
        for (int i2 = 0; i2 < 4; i2++) {
            int idx = lane + i2 * 32;
            int rr = idx >> 2, f = idx & 3;
            *(uint4*)(qs_h + rr * BVS + f * 8) =
                *(const uint4*)(q + baseBT + (size_t)(l0 + rr) * HD_ + f * 8);
        }
        __syncwarp();

        uint32_t af[2][2][4];
        #pragma unroll
        for (int mt = 0; mt < 2; mt++)
            #pragma unroll
            for (int s = 0; s < 2; s++)
                ldm_x4(af[mt][s], qsb + (mt * 16 + fr) * (BVS * 2) + s * 32 + fc);

        float acc[2][5][4];
        #pragma unroll
        for (int mt = 0; mt < 2; mt++)
            #pragma unroll
            for (int nt = 0; nt < 5; nt++)
                #pragma unroll
                for (int cc = 0; cc < 4; cc++) acc[mt][nt][cc] = 0.f;

        #pragma unroll
        for (int mt = 0; mt < 2; mt++)
            #pragma unroll
            for (int nt = 0; nt < 5; nt++) {
                int bn = nt >> 1, od = nt & 1;
                #pragma unroll
                for (int s = 0; s < 2; s++)
                    MMA_F16(acc[mt][nt],
                            af[mt][s][0], af[mt][s][1], af[mt][s][2], af[mt][s][3],
                            bf[bn][s][od], bf[bn][s][od + 2]);
            }

        #pragma unroll
        for (int mt = 0; mt < 2; mt++) {
            float dlo = __shfl_sync(0xffffffffu, acc[mt][4][0], lane & 28);
            float dhi = __shfl_sync(0xffffffffu, acc[mt][4][2], lane & 28);
            float ilo = 1.f / fmaxf(dlo + (float)N_, 1e-5f);
            float ihi = 1.f / fmaxf(dhi + (float)N_, 1e-5f);
            int tlo = l0 + mt * 16 + r;
            int thi = tlo + 8;
            #pragma unroll
            for (int nt = 0; nt < 4; nt++) {
                int d = nt * 8 + c2;
                float2 vl = h2f2(*(const uint32_t*)(v + baseBT + (size_t)tlo * HD_ + d));
                float2 vh = h2f2(*(const uint32_t*)(v + baseBT + (size_t)thi * HD_ + d));
                float r0 = (acc[mt][nt][0] + (float)N_ * vl.x) * ilo;
                float r1 = (acc[mt][nt][1] + (float)N_ * vl.y) * ilo;
                float r2 = (acc[mt][nt][2] + (float)N_ * vh.x) * ihi;
                float r3 = (acc[mt][nt][3] + (float)N_ * vh.y) * ihi;
                *(uint32_t*)(o + baseBT + (size_t)tlo * HD_ + d) = f2h2(r0, r1);
                *(uint32_t*)(o + baseBT + (size_t)thi * HD_ + d) = f2h2(r2, r3);
            }
        }
        __syncwarp();
    }
}

// ---------------------------------------------------------------------------
// Temporal linear attention (attend over T=24). Block = (b, n), warp = head.
// Head-major: base = ((h*B + b)*T*N + n)*32, t stride = N*32.
// ---------------------------------------------------------------------------
#define TKS 40
#define TVS 56
#define TPH 3200
#define TSM_BYTES (8 * TPH * 2)            // 51200
__global__ __launch_bounds__(256)
void temporal_attn_kernel(const __half* __restrict__ q, const __half* __restrict__ k,
                          const __half* __restrict__ v, __half* __restrict__ o)
{
    extern __shared__ __align__(16) __half smh[];
    const int bn = blockIdx.x;
    const int b = bn >> 11;
    const int n = bn & 2047;
    const int tid = threadIdx.x;
    const int h = tid >> 5, lane = tid & 31;

    __half* hb   = smh + h * TPH;
    __half* kst  = hb;
    __half* vst  = hb + 32 * TKS;
    __half* bv_h = hb;
    __half* qs_h = hb + 48 * BVS;

    const size_t base = (((size_t)h * B_ + b) * T_ * N_ + n) * HD_;
    const size_t sT = (size_t)N_ * HD_;

    const uint32_t kstb = smem_u32(kst);
    const uint32_t vstb = smem_u32(vst);

    {
        const uint4 z = make_uint4(0, 0, 0, 0);
        #pragma unroll
        for (int i = 0; i < 3; i++) {
            int idx = lane + i * 32;
            if (idx < 40) {
                int rr = idx / 5, cc = idx % 5;
                *(uint4*)(kst + (24 + rr) * TKS + cc * 8) = z;
            } else {
                int j = idx - 40;
                int rr = j / 7, cc = j % 7;
                *(uint4*)(vst + (24 + rr) * TVS + cc * 8) = z;
            }
        }
    }
    #pragma unroll
    for (int i = 0; i < 3; i++) {
        int idx = lane + i * 32;
        int t = idx >> 2, f = idx & 3;
        *(uint4*)(kst + t * TKS + f * 8) =
            *(const uint4*)(k + base + (size_t)t * sT + f * 8);
        *(uint4*)(vst + t * TVS + f * 8) =
            *(const uint4*)(v + base + (size_t)t * sT + f * 8);
    }
    if (lane < 24) vst[lane * TVS + 32] = __float2half(1.f);
    __syncwarp();

    const int fr_t = (lane & 7) + ((lane >> 4) & 1) * 8;
    const int fc_t = ((lane >> 3) & 1) * 16;

    float acc1[3][4][4];
    #pragma unroll
    for (int mi = 0; mi < 3; mi++)
        #pragma unroll
        for (int ni = 0; ni < 4; ni++)
            #pragma unroll
            for (int c = 0; c < 4; c++) acc1[mi][ni][c] = 0.f;

    #pragma unroll
    for (int s = 0; s < 2; s++) {
        uint32_t afr[3][4], bfr[2][4];
        #pragma unroll
        for (int mi = 0; mi < 3; mi++)
            ldm_x4_t(afr[mi], vstb + (s * 16 + fr_t) * (TVS * 2) + mi * 32 + fc_t);
        #pragma unroll
        for (int bi = 0; bi < 2; bi++)
            ldm_x4_t(bfr[bi], kstb + (s * 16 + fr_t) * (TKS * 2) + bi * 32 + fc_t);
        #pragma unroll
        for (int mi = 0; mi < 3; mi++)
            #pragma unroll
            for (int ni = 0; ni < 4; ni++) {
                int bi = ni >> 1, od = ni & 1;
                MMA_F16(acc1[mi][ni],
                        afr[mi][0], afr[mi][1], afr[mi][2], afr[mi][3],
                        bfr[bi][od], bfr[bi][od + 2]);
            }
    }
    __syncwarp();

    const int r  = lane >> 2;
    const int c2 = (lane & 3) << 1;

    #pragma unroll
    for (int mi = 0; mi < 3; mi++)
        #pragma unroll
        for (int ni = 0; ni < 4; ni++) {
            *(uint32_t*)(bv_h + (mi * 16 + r) * BVS + ni * 8 + c2) =
                f2h2(acc1[mi][ni][0], acc1[mi][ni][1]);
            *(uint32_t*)(bv_h + (mi * 16 + r + 8) * BVS + ni * 8 + c2) =
                f2h2(acc1[mi][ni][2], acc1[mi][ni][3]);
        }
    #pragma unroll
    for (int i = 0; i < 3; i++) {
        int idx = lane + i * 32;
        int t = idx >> 2, f = idx & 3;
        *(uint4*)(qs_h + t * BVS + f * 8) =
            *(const uint4*)(q + base + (size_t)t * sT + f * 8);
    }
    __syncwarp();

    const int fr = lane & 15;
    const int fc = (lane >> 4) * 16;

    const uint32_t bvb = smem_u32(bv_h);
    const uint32_t qsb = smem_u32(qs_h);

    uint32_t bf[3][2][4], af[2][2][4];
    #pragma unroll
    for (int bn2 = 0; bn2 < 3; bn2++)
        #pragma unroll
        for (int s = 0; s < 2; s++)
            ldm_x4(bf[bn2][s], bvb + (bn2 * 16 + fr) * (BVS * 2) + s * 32 + fc);
    #pragma unroll
    for (int mt = 0; mt < 2; mt++)
        #pragma unroll
        for (int s = 0; s < 2; s++)
            ldm_x4(af[mt][s], qsb + (mt * 16 + fr) * (BVS * 2) + s * 32 + fc);

    float acc[2][5][4];
    #pragma unroll
    for (int mt = 0; mt < 2; mt++)
        #pragma unroll
        for (int nt = 0; nt < 5; nt++)
            #pragma unroll
            for (int cc = 0; cc < 4; cc++) acc[mt][nt][cc] = 0.f;

    #pragma unroll
    for (int mt = 0; mt < 2; mt++)
        #pragma unroll
        for (int nt = 0; nt < 5; nt++) {
            int bn2 = nt >> 1, od = nt & 1;
            #pragma unroll
            for (int s = 0; s < 2; s++)
                MMA_F16(acc[mt][nt],
                        af[mt][s][0], af[mt][s][1], af[mt][s][2], af[mt][s][3],
                        bf[bn2][s][od], bf[bn2][s][od + 2]);
        }

    #pragma unroll
    for (int mt = 0; mt < 2; mt++) {
        float dlo = __shfl_sync(0xffffffffu, acc[mt][4][0], lane & 28);
        float dhi = __shfl_sync(0xffffffffu, acc[mt][4][2], lane & 28);
        float ilo = 1.f / fmaxf(dlo + (float)T_, 1e-5f);
        float ihi = 1.f / fmaxf(dhi + (float)T_, 1e-5f);
        int tlo = mt * 16 + r;
        int thi = tlo + 8;
        bool hiv = (thi < T_);
        #pragma unroll
        for (int nt = 0; nt < 4; nt++) {
            int d = nt * 8 + c2;
            float2 vl = h2f2(*(const uint32_t*)(v + base + (size_t)tlo * sT + d));
            float r0 = (acc[mt][nt][0] + (float)T_ * vl.x) * ilo;
            float r1 = (acc[mt][nt][1] + (float)T_ * vl.y) * ilo;
            *(uint32_t*)(o + base + (size_t)tlo * sT + d) = f2h2(r0, r1);
            if (hiv) {
                float2 vh = h2f2(*(const uint32_t*)(v + base + (size_t)thi * sT + d));
                float r2 = (acc[mt][nt][2] + (float)T_ * vh.x) * ihi;
                float r3 = (acc[mt][nt][3] + (float)T_ * vh.y) * ihi;
                *(uint32_t*)(o + base + (size_t)thi * sT + d) = f2h2(r2, r3);
            }
        }
    }
}

// ---------------------------------------------------------------------------
extern "C" void kernel_launch(void* const* d_in, const int* in_sizes, int n_in,
                              void* d_out, int out_size)
{
    const float* x     = (const float*)d_in[0];
    const float* w_qkv = (const float*)d_in[1];
    const float* w_out = (const float*)d_in[2];
    const float* b_out = (const float*)d_in[3];
    float* out = (float*)d_out;

    __half *q, *k, *v, *os, *ot, *wqh, *woh;
    cudaGetSymbolAddress((void**)&q,   g_q);
    cudaGetSymbolAddress((void**)&k,   g_k);
    cudaGetSymbolAddress((void**)&v,   g_v);
    cudaGetSymbolAddress((void**)&os,  g_os);
    cudaGetSymbolAddress((void**)&ot,  g_ot);
    cudaGetSymbolAddress((void**)&wqh, g_wqh);
    cudaGetSymbolAddress((void**)&woh, g_woh);

    cudaFuncSetAttribute(gemm_qkv_kernel,
                         cudaFuncAttributeMaxDynamicSharedMemorySize, G1_SMEM);
    cudaFuncSetAttribute(gemm_out_kernel,
                         cudaFuncAttributeMaxDynamicSharedMemorySize, G2_SMEM);
    cudaFuncSetAttribute(temporal_attn_kernel,
                         cudaFuncAttributeMaxDynamicSharedMemorySize, TSM_BYTES);

    // 0) convert weights to fp16 scratch
    {
        int total = (768 * 256 + 256 * 512) / 2;
        cvt_weights_kernel<<<(total + 255) / 256, 256>>>(w_qkv, w_out, wqh, woh);
    }
    // 1) QKV projection (head-major outputs) + fused q/k l2norm
    gemm_qkv_kernel<<<MTOK / 128, 256, G1_SMEM>>>(x, wqh, q, k, v);

    // 2) spatial attention (fully coalesced head-major access)
    {
        dim3 grid(B_ * T_, H_);
        spatial_attn_kernel<<<grid, 256>>>(q, k, v, os);
    }
    // 3) temporal attention
    temporal_attn_kernel<<<B_ * N_, 256, TSM_BYTES>>>(q, k, v, ot);

    // 4) output projection + bias (head-major A operands)
    {
        dim3 grid(2, MTOK / 128);
        gemm_out_kernel<<<grid, 256, G2_SMEM>>>(os, ot, woh, b_out, out);
    }
}

// round 17
// speedup vs baseline: 1.2314x; 1.0067x over previous
#include <cuda_runtime.h>
#include <cuda_fp16.h>
#include <math.h>
#include <stdint.h>

#define B_  4
#define T_  24
#define N_  2048
#define D_  256
#define H_  8
#define HD_ 32
#define MTOK (B_*T_*N_)           // 196608 tokens
#define ELEMS ((size_t)MTOK * D_) // 50,331,648

// Scratch (device globals). Head-major layout: [h][token][32] halfs.
__device__ __half g_q [ELEMS];
__device__ __half g_k [ELEMS];
__device__ __half g_v [ELEMS];
__device__ __half g_os[ELEMS];
__device__ __half g_ot[ELEMS];
__device__ __half g_wqh[768*256];
__device__ __half g_woh[256*512];

// ---------------------------------------------------------------------------
// helpers
// ---------------------------------------------------------------------------
__device__ __forceinline__ uint32_t smem_u32(const void* p) {
    uint32_t a;
    asm("{ .reg .u64 t; cvta.to.shared.u64 t, %1; cvt.u32.u64 %0, t; }"
        : "=r"(a) : "l"(p));
    return a;
}
__device__ __forceinline__ uint32_t f2h2(float a, float b) {
    __half2 h = __floats2half2_rn(a, b);
    return *(uint32_t*)&h;
}
__device__ __forceinline__ uint2 f4h(float4 v) {
    return make_uint2(f2h2(v.x, v.y), f2h2(v.z, v.w));
}
__device__ __forceinline__ float2 h2f2(uint32_t h) {
    return __half22float2(*(__half2*)&h);
}
__device__ __forceinline__ void ldm_x4(uint32_t* r, uint32_t addr) {
    asm volatile("ldmatrix.sync.aligned.m8n8.x4.shared.b16 {%0,%1,%2,%3}, [%4];"
                 : "=r"(r[0]), "=r"(r[1]), "=r"(r[2]), "=r"(r[3]) : "r"(addr));
}
__device__ __forceinline__ void ldm_x4_t(uint32_t* r, uint32_t addr) {
    asm volatile("ldmatrix.sync.aligned.m8n8.x4.trans.shared.b16 {%0,%1,%2,%3}, [%4];"
                 : "=r"(r[0]), "=r"(r[1]), "=r"(r[2]), "=r"(r[3]) : "r"(addr));
}
#define MMA_F16(d, a0, a1, a2, a3, b0, b1)                                    \
    asm volatile("mma.sync.aligned.m16n8k16.row.col.f32.f16.f16.f32 "         \
                 "{%0,%1,%2,%3}, {%4,%5,%6,%7}, {%8,%9}, {%0,%1,%2,%3};"      \
                 : "+f"(d[0]), "+f"(d[1]), "+f"(d[2]), "+f"(d[3])             \
                 : "r"(a0), "r"(a1), "r"(a2), "r"(a3), "r"(b0), "r"(b1))

// ---- cp.async (L2 -> SMEM, 16B) ----
__device__ __forceinline__ void cp16(uint32_t saddr, const void* gaddr) {
    asm volatile("cp.async.cg.shared.global [%0], [%1], 16;"
                 :: "r"(saddr), "l"(gaddr) : "memory");
}
#define CP_COMMIT() asm volatile("cp.async.commit_group;" ::: "memory")
#define CP_WAIT0()  asm volatile("cp.async.wait_group 0;" ::: "memory")

// Row strides: 80B (chunk tiles) and 528B (resident A). Both ≡16 (mod 128).
#define CH_STRIDE 80
#define CH_BYTES  (128*CH_STRIDE)
#define AR_STRIDE 528
#define AR_BYTES  (128*AR_STRIDE)

// ---------------------------------------------------------------------------
// weight pre-conversion: f32 -> f16 (once per launch)
// ---------------------------------------------------------------------------
__global__ void cvt_weights_kernel(const float* __restrict__ wq,
                                   const float* __restrict__ wo,
                                   __half* __restrict__ wqh,
                                   __half* __restrict__ woh)
{
    int i = blockIdx.x * blockDim.x + threadIdx.x;
    const int NQ = 768 * 256 / 2;
    const int NO = 256 * 512 / 2;
    if (i < NQ) {
        float2 f = *(const float2*)(wq + i * 2);
        *(uint32_t*)(wqh + i * 2) = f2h2(f.x, f.y);
    } else if (i < NQ + NO) {
        int j = i - NQ;
        float2 f = *(const float2*)(wo + j * 2);
        *(uint32_t*)(woh + j * 2) = f2h2(f.x, f.y);
    }
}

// ===========================================================================
// GEMM1 (A-resident, fp16): qkv[M,768] = x[M,256] * w_qkv[768,256]^T
// Outputs written head-major: dst[h][m][32].
// ===========================================================================
#define G1_SMEM (AR_BYTES + 2*CH_BYTES)   // 88064

__global__ __launch_bounds__(256, 2)
void gemm_qkv_kernel(const float* __restrict__ A, const __half* __restrict__ Bw,
                     __half* __restrict__ outq, __half* __restrict__ outk,
                     __half* __restrict__ outv)
{
    extern __shared__ __align__(16) char smem[];
    const uint32_t sbase = smem_u32(smem);
    const int tid  = threadIdx.x;
    const int lane = tid & 31;
    const int wid  = tid >> 5;
    const int wm   = wid & 1;
    const int wn   = wid >> 1;
    const int m0   = blockIdx.x * 128;

    const int ar = tid >> 1;
    const int ac = tid & 1;
    const int fr = lane & 15;
    const int fc = (lane >> 4) * 16;
    const int r  = lane >> 2;
    const int c2 = (lane & 3) << 1;

    // ---- prologue: A (128x256 f32) -> resident fp16 smem, once ----
    #pragma unroll
    for (int j = 0; j < 8; j++) {
        const float* ap = A + (size_t)(m0 + ar) * 256 + (ac * 8 + j) * 16;
        uint2 h0 = f4h(*(const float4*)(ap + 0));
        uint2 h1 = f4h(*(const float4*)(ap + 4));
        uint2 h2 = f4h(*(const float4*)(ap + 8));
        uint2 h3 = f4h(*(const float4*)(ap + 12));
        char* dst = smem + ar * AR_STRIDE + (ac * 8 + j) * 32;
        *(uint4*)(dst)      = make_uint4(h0.x, h0.y, h1.x, h1.y);
        *(uint4*)(dst + 16) = make_uint4(h2.x, h2.y, h3.x, h3.y);
    }

    auto cpB = [&](int it, int buf) {
        const int nt = it >> 3, kt = it & 7;
        const __half* bp = Bw + (size_t)(nt * 128 + ar) * 256 + kt * 32 + ac * 16;
        uint32_t dst = sbase + AR_BYTES + buf * CH_BYTES + ar * CH_STRIDE + ac * 32;
        cp16(dst, bp);
        cp16(dst + 16, bp + 8);
        CP_COMMIT();
    };

    float acc[4][4][4];
    #pragma unroll
    for (int i = 0; i < 4; i++)
        #pragma unroll
        for (int j = 0; j < 4; j++)
            #pragma unroll
            for (int c = 0; c < 4; c++) acc[i][j][c] = 0.f;

    cpB(0, 0);
    CP_WAIT0();
    __syncthreads();

    #pragma unroll 1
    for (int it = 0; it < 48; it++) {
        if (it + 1 < 48) cpB(it + 1, (it + 1) & 1);

        {
            const int kt = it & 7;
            const uint32_t abase = sbase + kt * 64;
            const uint32_t bbase = sbase + AR_BYTES + (it & 1) * CH_BYTES;
            #pragma unroll
            for (int s = 0; s < 2; s++) {
                uint32_t af[4][4], bf[2][4];
                #pragma unroll
                for (int mt = 0; mt < 4; mt++) {
                    int row = wm * 64 + mt * 16 + fr;
                    ldm_x4(af[mt], abase + row * AR_STRIDE + s * 32 + fc);
                }
                #pragma unroll
                for (int bi = 0; bi < 2; bi++) {
                    int row = wn * 32 + bi * 16 + fr;
                    ldm_x4(bf[bi], bbase + row * CH_STRIDE + s * 32 + fc);
                }
                #pragma unroll
                for (int mt = 0; mt < 4; mt++)
                    #pragma unroll
                    for (int nt2 = 0; nt2 < 4; nt2++) {
                        int bi = nt2 >> 1, od = nt2 & 1;
                        MMA_F16(acc[mt][nt2],
                                af[mt][0], af[mt][1], af[mt][2], af[mt][3],
                                bf[bi][od], bf[bi][od + 2]);
                    }
            }
        }

        if ((it & 7) == 7) {
            const int tile = it >> 3;
            const int sel  = tile >> 1;
            const int hh   = wn + 4 * (tile & 1);

            if (sel < 2) {
                #pragma unroll
                for (int mt = 0; mt < 4; mt++) {
                    float sslo = 0.f, sshi = 0.f;
                    #pragma unroll
                    for (int nt2 = 0; nt2 < 4; nt2++) {
                        sslo = fmaf(acc[mt][nt2][0], acc[mt][nt2][0], sslo);
                        sslo = fmaf(acc[mt][nt2][1], acc[mt][nt2][1], sslo);
                        sshi = fmaf(acc[mt][nt2][2], acc[mt][nt2][2], sshi);
                        sshi = fmaf(acc[mt][nt2][3], acc[mt][nt2][3], sshi);
                    }
                    sslo += __shfl_xor_sync(0xffffffffu, sslo, 1);
                    sslo += __shfl_xor_sync(0xffffffffu, sslo, 2);
                    sshi += __shfl_xor_sync(0xffffffffu, sshi, 1);
                    sshi += __shfl_xor_sync(0xffffffffu, sshi, 2);
                    float slo = 1.f / fmaxf(sqrtf(sslo), 1e-12f);
                    float shi = 1.f / fmaxf(sqrtf(sshi), 1e-12f);
                    #pragma unroll
                    for (int nt2 = 0; nt2 < 4; nt2++) {
                        acc[mt][nt2][0] *= slo; acc[mt][nt2][1] *= slo;
                        acc[mt][nt2][2] *= shi; acc[mt][nt2][3] *= shi;
                    }
                }
            }

            __half* dstb = (sel == 0) ? outq : ((sel == 1) ? outk : outv);
            __half* dsth = dstb + (size_t)hh * MTOK * HD_;
            #pragma unroll
            for (int mt = 0; mt < 4; mt++) {
                int m = m0 + wm * 64 + mt * 16 + r;
                #pragma unroll
                for (int nt2 = 0; nt2 < 4; nt2++) {
                    int cc = nt2 * 8 + c2;
                    float* a = acc[mt][nt2];
                    *(uint32_t*)(dsth + (size_t)m * HD_ + cc)       = f2h2(a[0], a[1]);
                    *(uint32_t*)(dsth + (size_t)(m + 8) * HD_ + cc) = f2h2(a[2], a[3]);
                    a[0] = a[1] = a[2] = a[3] = 0.f;
                }
            }
        }

        if (it + 1 < 48) CP_WAIT0();
        __syncthreads();
    }
}

// ===========================================================================
// GEMM2 (fp16 in / f32 out): out = [os|ot] * w_out^T + b
// ===========================================================================
#define G2_SMEM (4*CH_BYTES)   // 40960

__global__ __launch_bounds__(256, 2)
void gemm_out_kernel(const __half* __restrict__ A0, const __half* __restrict__ A1,
                     const __half* __restrict__ Bw,
                     const float* __restrict__ bias,
                     float* __restrict__ out)
{
    extern __shared__ __align__(16) char smem[];
    const uint32_t sbase = smem_u32(smem);
    const int tid  = threadIdx.x;
    const int lane = tid & 31;
    const int wid  = tid >> 5;
    const int wm   = wid & 1;
    const int wn   = wid >> 1;
    const int m0   = blockIdx.y * 128;
    const int n0g  = blockIdx.x * 128;

    const int ar = tid >> 1;
    const int ac = tid & 1;
    const int fr = lane & 15;
    const int fc = (lane >> 4) * 16;
    const int r  = lane >> 2;
    const int c2 = (lane & 3) << 1;

    auto cpAB = [&](int kt, int buf) {
        const int k0 = kt * 32;
        const __half* Asrc = (k0 < 256) ? A0 : A1;
        const int hh = kt & 7;
        const __half* ap = Asrc + ((size_t)hh * MTOK + m0 + ar) * HD_ + ac * 16;
        uint32_t da = sbase + buf * 2 * CH_BYTES + ar * CH_STRIDE + ac * 32;
        cp16(da, ap);
        cp16(da + 16, ap + 8);
        const __half* bp = Bw + (size_t)(n0g + ar) * 512 + k0 + ac * 16;
        uint32_t db = da + CH_BYTES;
        cp16(db, bp);
        cp16(db + 16, bp + 8);
        CP_COMMIT();
    };

    float acc[4][4][4];
    #pragma unroll
    for (int i = 0; i < 4; i++)
        #pragma unroll
        for (int j = 0; j < 4; j++)
            #pragma unroll
            for (int c = 0; c < 4; c++) acc[i][j][c] = 0.f;

    cpAB(0, 0);
    CP_WAIT0();
    __syncthreads();

    #pragma unroll 1
    for (int kt = 0; kt < 16; kt++) {
        if (kt + 1 < 16) cpAB(kt + 1, (kt + 1) & 1);

        {
            const uint32_t abase = sbase + (kt & 1) * 2 * CH_BYTES;
            const uint32_t bbase = abase + CH_BYTES;
            #pragma unroll
            for (int s = 0; s < 2; s++) {
                uint32_t af[4][4], bf[2][4];
                #pragma unroll
                for (int mt = 0; mt < 4; mt++) {
                    int row = wm * 64 + mt * 16 + fr;
                    ldm_x4(af[mt], abase + row * CH_STRIDE + s * 32 + fc);
                }
                #pragma unroll
                for (int bi = 0; bi < 2; bi++) {
                    int row = wn * 32 + bi * 16 + fr;
                    ldm_x4(bf[bi], bbase + row * CH_STRIDE + s * 32 + fc);
                }
                #pragma unroll
                for (int mt = 0; mt < 4; mt++)
                    #pragma unroll
                    for (int nt2 = 0; nt2 < 4; nt2++) {
                        int bi = nt2 >> 1, od = nt2 & 1;
                        MMA_F16(acc[mt][nt2],
                                af[mt][0], af[mt][1], af[mt][2], af[mt][3],
                                bf[bi][od], bf[bi][od + 2]);
                    }
            }
        }

        if (kt + 1 < 16) CP_WAIT0();
        __syncthreads();
    }

    #pragma unroll
    for (int mt = 0; mt < 4; mt++) {
        int m = m0 + wm * 64 + mt * 16 + r;
        #pragma unroll
        for (int nt = 0; nt < 4; nt++) {
            int n = n0g + wn * 32 + nt * 8 + c2;
            float* a = acc[mt][nt];
            float b0 = bias[n], b1 = bias[n + 1];
            *(float2*)(out + (size_t)m * 256 + n)       = make_float2(a[0] + b0, a[1] + b1);
            *(float2*)(out + (size_t)(m + 8) * 256 + n) = make_float2(a[2] + b0, a[3] + b1);
        }
    }
}

// ===========================================================================
// Fused attention kernel: blocks [0,768) = spatial, [768, 8960) = temporal.
// Shared dynamic smem arena (51200 B), 256 threads.
// ===========================================================================
#define BVS 40
#define KST_S 40
#define VST_S 56
#define TKS 40
#define TVS 56
#define TPH 3200
#define ATT_SMEM (8 * TPH * 2)   // 51200 >= spatial need (45440)

// ---- spatial body (block = (bt, h), 8 warps) ----
__device__ __forceinline__
void spatial_body(char* dynsm, int bid,
                  const __half* __restrict__ q, const __half* __restrict__ k,
                  const __half* __restrict__ v, __half* __restrict__ o)
{
    // carve arena
    float (*s_part)[32][36] = (float(*)[32][36])dynsm;                 // 36864
    float (*s_kvs)[36]      = (float(*)[36])(dynsm + 36864);           // 4608
    float* s_kss            = (float*)(dynsm + 36864 + 4608);          // 128
    __half* s_bv            = (__half*)(dynsm + 36864 + 4608 + 128);   // 3840

    const int bt = bid % (B_ * T_);
    const int h  = bid / (B_ * T_);
    const int tid = threadIdx.x;
    const int w = tid >> 5, lane = tid & 31;

    const size_t baseBT = ((size_t)h * (B_ * T_) + bt) * N_ * HD_;
    const int l0w = w * 256;

    char* wb = (char*)&s_part[w][0][0];
    __half* kst = (__half*)wb;
    __half* vst = (__half*)(wb + 16 * KST_S * 2);
    const uint32_t kstb = smem_u32(kst);
    const uint32_t vstb = smem_u32(vst);

    if (lane < 16) vst[lane * VST_S + 32] = __float2half(1.f);
    __syncwarp();

    const int fr_t = (lane & 7) + ((lane >> 4) & 1) * 8;
    const int fc_t = ((lane >> 3) & 1) * 16;

    float acc1[2][5][4];
    #pragma unroll
    for (int mt = 0; mt < 2; mt++)
        #pragma unroll
        for (int nt = 0; nt < 5; nt++)
            #pragma unroll
            for (int c = 0; c < 4; c++) acc1[mt][nt][c] = 0.f;

    const int crow = lane >> 2;
    const int cq4  = (lane & 3) * 8;

    uint4 kr2[2], vr2[2];
    auto ldgkv = [&](int c16) {
        int l0c = l0w + c16 * 16;
        #pragma unroll
        for (int i = 0; i < 2; i++) {
            int row = l0c + crow + i * 8;
            kr2[i] = *(const uint4*)(k + baseBT + (size_t)row * HD_ + cq4);
            vr2[i] = *(const uint4*)(v + baseBT + (size_t)row * HD_ + cq4);
        }
    };
    auto stskv = [&]() {
        #pragma unroll
        for (int i = 0; i < 2; i++) {
            int row = crow + i * 8;
            *(uint4*)(kst + row * KST_S + cq4) = kr2[i];
            *(uint4*)(vst + row * VST_S + cq4) = vr2[i];
        }
    };

    ldgkv(0); stskv(); __syncwarp();
    #pragma unroll 1
    for (int c16 = 0; c16 < 16; c16++) {
        if (c16 + 1 < 16) ldgkv(c16 + 1);

        uint32_t afr[2][4], bfr[3][4];
        ldm_x4_t(afr[0], kstb + fr_t * (KST_S * 2) + fc_t);
        ldm_x4_t(afr[1], kstb + fr_t * (KST_S * 2) + 32 + fc_t);
        ldm_x4_t(bfr[0], vstb + fr_t * (VST_S * 2) + fc_t);
        ldm_x4_t(bfr[1], vstb + fr_t * (VST_S * 2) + 32 + fc_t);
        ldm_x4_t(bfr[2], vstb + fr_t * (VST_S * 2) + 64 + fc_t);

        #pragma unroll
        for (int mt = 0; mt < 2; mt++)
            #pragma unroll
            for (int nt = 0; nt < 5; nt++) {
                int bn = nt >> 1, od = nt & 1;
                MMA_F16(acc1[mt][nt],
                        afr[mt][0], afr[mt][1], afr[mt][2], afr[mt][3],
                        bfr[bn][od], bfr[bn][od + 2]);
            }

        if (c16 + 1 < 16) {
            __syncwarp();
            stskv();
        }
        __syncwarp();
    }

    {
        const int r = lane >> 2;
        const int c2l = (lane & 3) << 1;
        #pragma unroll
        for (int mt = 0; mt < 2; mt++) {
            #pragma unroll
            for (int nt = 0; nt < 4; nt++) {
                *(float2*)&s_part[w][mt*16 + r][nt*8 + c2l] =
                    make_float2(acc1[mt][nt][0], acc1[mt][nt][1]);
                *(float2*)&s_part[w][mt*16 + r + 8][nt*8 + c2l] =
                    make_float2(acc1[mt][nt][2], acc1[mt][nt][3]);
            }
            if (c2l == 0) {
                s_part[w][mt*16 + r][32]     = acc1[mt][4][0];
                s_part[w][mt*16 + r + 8][32] = acc1[mt][4][2];
            }
        }
    }
    __syncthreads();

    {
        int m = tid >> 3, dd = (tid & 7) * 4;
        float4 s = make_float4(0.f, 0.f, 0.f, 0.f);
        #pragma unroll
        for (int wi = 0; wi < 8; wi++) {
            float4 p = *(const float4*)&s_part[wi][m][dd];
            s.x += p.x; s.y += p.y; s.z += p.z; s.w += p.w;
        }
        *(float4*)&s_kvs[m][dd] = s;
        if (tid < 32) {
            float s2 = 0.f;
            #pragma unroll
            for (int wi = 0; wi < 8; wi++) s2 += s_part[wi][tid][32];
            s_kss[tid] = s2;
        }
    }
    __syncthreads();

    for (int idx = tid; idx < 33 * 32; idx += 256) {
        int nn = idx >> 5, m = idx & 31;
        float val = (nn < 32) ? s_kvs[m][nn] : s_kss[m];
        s_bv[nn * BVS + m] = __float2half(val);
    }
    __syncthreads();

    const int fr = lane & 15;
    const int fc = (lane >> 4) * 16;
    const int r  = lane >> 2;
    const int c2 = (lane & 3) << 1;

    const uint32_t bvb = smem_u32(s_bv);
    uint32_t bf[3][2][4];
    #pragma unroll
    for (int bn = 0; bn < 3; bn++)
        #pragma unroll
        for (int s = 0; s < 2; s++)
            ldm_x4(bf[bn][s], bvb + (bn * 16 + fr) * (BVS * 2) + s * 32 + fc);

    __half* qs_h = (__half*)&s_part[w][0][0];
    const uint32_t qsb = smem_u32(qs_h);

    for (int c = 0; c < 8; c++) {
        const int l0 = l0w + c * 32;
        #pragma unroll
        for (int i2 = 0; i2 < 4; i2++) {
            int idx = lane + i2 * 32;
            int rr = idx >> 2, f = idx & 3;
            *(uint4*)(qs_h + rr * BVS + f * 8) =
                *(const uint4*)(q + baseBT + (size_t)(l0 + rr) * HD_ + f * 8);
        }
        __syncwarp();

        uint32_t af[2][2][4];
        #pragma unroll
        for (int mt = 0; mt < 2; mt++)
            #pragma unroll
            for (int s = 0; s < 2; s++)
                ldm_x4(af[mt][s], qsb + (mt * 16 + fr) * (BVS * 2) + s * 32 + fc);

        float acc[2][5][4];
        #pragma unroll
        for (int mt = 0; mt < 2; mt++)
            #pragma unroll
            for (int nt = 0; nt < 5; nt++)
                #pragma unroll
                for (int cc = 0; cc < 4; cc++) acc[mt][nt][cc] = 0.f;

        #pragma unroll
        for (int mt = 0; mt < 2; mt++)
            #pragma unroll
            for (int nt = 0; nt < 5; nt++) {
                int bn = nt >> 1, od = nt & 1;
                #pragma unroll
                for (int s = 0; s < 2; s++)
                    MMA_F16(acc[mt][nt],
                            af[mt][s][0], af[mt][s][1], af[mt][s][2], af[mt][s][3],
                            bf[bn][s][od], bf[bn][s][od + 2]);
            }

        #pragma unroll
        for (int mt = 0; mt < 2; mt++) {
            float dlo = __shfl_sync(0xffffffffu, acc[mt][4][0], lane & 28);
            float dhi = __shfl_sync(0xffffffffu, acc[mt][4][2], lane & 28);
            float ilo = 1.f / fmaxf(dlo + (float)N_, 1e-5f);
            float ihi = 1.f / fmaxf(dhi + (float)N_, 1e-5f);
            int tlo = l0 + mt * 16 + r;
            int thi = tlo + 8;
            #pragma unroll
            for (int nt = 0; nt < 4; nt++) {
                int d = nt * 8 + c2;
                float2 vl = h2f2(*(const uint32_t*)(v + baseBT + (size_t)tlo * HD_ + d));
                float2 vh = h2f2(*(const uint32_t*)(v + baseBT + (size_t)thi * HD_ + d));
                float r0 = (acc[mt][nt][0] + (float)N_ * vl.x) * ilo;
                float r1 = (acc[mt][nt][1] + (float)N_ * vl.y) * ilo;
                float r2 = (acc[mt][nt][2] + (float)N_ * vh.x) * ihi;
                float r3 = (acc[mt][nt][3] + (float)N_ * vh.y) * ihi;
                *(uint32_t*)(o + baseBT + (size_t)tlo * HD_ + d) = f2h2(r0, r1);
                *(uint32_t*)(o + baseBT + (size_t)thi * HD_ + d) = f2h2(r2, r3);
            }
        }
        __syncwarp();
    }
}

// ---- temporal body (block = (b, n), warp = head) ----
__device__ __forceinline__
void temporal_body(char* dynsm, int bn,
                   const __half* __restrict__ q, const __half* __restrict__ k,
                   const __half* __restrict__ v, __half* __restrict__ o)
{
    __half* smh = (__half*)dynsm;
    const int b = bn >> 11;
    const int n = bn & 2047;
    const int tid = threadIdx.x;
    const int h = tid >> 5, lane = tid & 31;

    __half* hb   = smh + h * TPH;
    __half* kst  = hb;
    __half* vst  = hb + 32 * TKS;
    __half* bv_h = hb;
    __half* qs_h = hb + 48 * BVS;

    const size_t base = (((size_t)h * B_ + b) * T_ * N_ + n) * HD_;
    const size_t sT = (size_t)N_ * HD_;

    const uint32_t kstb = smem_u32(kst);
    const uint32_t vstb = smem_u32(vst);

    {
        const uint4 z = make_uint4(0, 0, 0, 0);
        #pragma unroll
        for (int i = 0; i < 3; i++) {
            int idx = lane + i * 32;
            if (idx < 40) {
                int rr = idx / 5, cc = idx % 5;
                *(uint4*)(kst + (24 + rr) * TKS + cc * 8) = z;
            } else {
                int j = idx - 40;
                int rr = j / 7, cc = j % 7;
                *(uint4*)(vst + (24 + rr) * TVS + cc * 8) = z;
            }
        }
    }
    #pragma unroll
    for (int i = 0; i < 3; i++) {
        int idx = lane + i * 32;
        int t = idx >> 2, f = idx & 3;
        *(uint4*)(kst + t * TKS + f * 8) =
            *(const uint4*)(k + base + (size_t)t * sT + f * 8);
        *(uint4*)(vst + t * TVS + f * 8) =
            *(const uint4*)(v + base + (size_t)t * sT + f * 8);
    }
    if (lane < 24) vst[lane * TVS + 32] = __float2half(1.f);
    __syncwarp();

    const int fr_t = (lane & 7) + ((lane >> 4) & 1) * 8;
    const int fc_t = ((lane >> 3) & 1) * 16;

    float acc1[3][4][4];
    #pragma unroll
    for (int mi = 0; mi < 3; mi++)
        #pragma unroll
        for (int ni = 0; ni < 4; ni++)
            #pragma unroll
            for (int c = 0; c < 4; c++) acc1[mi][ni][c] = 0.f;

    #pragma unroll
    for (int s = 0; s < 2; s++) {
        uint32_t afr[3][4], bfr[2][4];
        #pragma unroll
        for (int mi = 0; mi < 3; mi++)
            ldm_x4_t(afr[mi], vstb + (s * 16 + fr_t) * (TVS * 2) + mi * 32 + fc_t);
        #pragma unroll
        for (int bi = 0; bi < 2; bi++)
            ldm_x4_t(bfr[bi], kstb + (s * 16 + fr_t) * (TKS * 2) + bi * 32 + fc_t);
        #pragma unroll
        for (int mi = 0; mi < 3; mi++)
            #pragma unroll
            for (int ni = 0; ni < 4; ni++) {
                int bi = ni >> 1, od = ni & 1;
                MMA_F16(acc1[mi][ni],
                        afr[mi][0], afr[mi][1], afr[mi][2], afr[mi][3],
                        bfr[bi][od], bfr[bi][od + 2]);
            }
    }
    __syncwarp();

    const int r  = lane >> 2;
    const int c2 = (lane & 3) << 1;

    #pragma unroll
    for (int mi = 0; mi < 3; mi++)
        #pragma unroll
        for (int ni = 0; ni < 4; ni++) {
            *(uint32_t*)(bv_h + (mi * 16 + r) * BVS + ni * 8 + c2) =
                f2h2(acc1[mi][ni][0], acc1[mi][ni][1]);
            *(uint32_t*)(bv_h + (mi * 16 + r + 8) * BVS + ni * 8 + c2) =
                f2h2(acc1[mi][ni][2], acc1[mi][ni][3]);
        }
    #pragma unroll
    for (int i = 0; i < 3; i++) {
        int idx = lane + i * 32;
        int t = idx >> 2, f = idx & 3;
        *(uint4*)(qs_h + t * BVS + f * 8) =
            *(const uint4*)(q + base + (size_t)t * sT + f * 8);
    }
    __syncwarp();

    const int fr = lane & 15;
    const int fc = (lane >> 4) * 16;

    const uint32_t bvb = smem_u32(bv_h);
    const uint32_t qsb = smem_u32(qs_h);

    uint32_t bf[3][2][4], af[2][2][4];
    #pragma unroll
    for (int bn2 = 0; bn2 < 3; bn2++)
        #pragma unroll
        for (int s = 0; s < 2; s++)
            ldm_x4(bf[bn2][s], bvb + (bn2 * 16 + fr) * (BVS * 2) + s * 32 + fc);
    #pragma unroll
    for (int mt = 0; mt < 2; mt++)
        #pragma unroll
        for (int s = 0; s < 2; s++)
            ldm_x4(af[mt][s], qsb + (mt * 16 + fr) * (BVS * 2) + s * 32 + fc);

    float acc[2][5][4];
    #pragma unroll
    for (int mt = 0; mt < 2; mt++)
        #pragma unroll
        for (int nt = 0; nt < 5; nt++)
            #pragma unroll
            for (int cc = 0; cc < 4; cc++) acc[mt][nt][cc] = 0.f;

    #pragma unroll
    for (int mt = 0; mt < 2; mt++)
        #pragma unroll
        for (int nt = 0; nt < 5; nt++) {
            int bn2 = nt >> 1, od = nt & 1;
            #pragma unroll
            for (int s = 0; s < 2; s++)
                MMA_F16(acc[mt][nt],
                        af[mt][s][0], af[mt][s][1], af[mt][s][2], af[mt][s][3],
                        bf[bn2][s][od], bf[bn2][s][od + 2]);
        }

    #pragma unroll
    for (int mt = 0; mt < 2; mt++) {
        float dlo = __shfl_sync(0xffffffffu, acc[mt][4][0], lane & 28);
        float dhi = __shfl_sync(0xffffffffu, acc[mt][4][2], lane & 28);
        float ilo = 1.f / fmaxf(dlo + (float)T_, 1e-5f);
        float ihi = 1.f / fmaxf(dhi + (float)T_, 1e-5f);
        int tlo = mt * 16 + r;
        int thi = tlo + 8;
        bool hiv = (thi < T_);
        #pragma unroll
        for (int nt = 0; nt < 4; nt++) {
            int d = nt * 8 + c2;
            float2 vl = h2f2(*(const uint32_t*)(v + base + (size_t)tlo * sT + d));
            float r0 = (acc[mt][nt][0] + (float)T_ * vl.x) * ilo;
            float r1 = (acc[mt][nt][1] + (float)T_ * vl.y) * ilo;
            *(uint32_t*)(o + base + (size_t)tlo * sT + d) = f2h2(r0, r1);
            if (hiv) {
                float2 vh = h2f2(*(const uint32_t*)(v + base + (size_t)thi * sT + d));
                float r2 = (acc[mt][nt][2] + (float)T_ * vh.x) * ihi;
                float r3 = (acc[mt][nt][3] + (float)T_ * vh.y) * ihi;
                *(uint32_t*)(o + base + (size_t)thi * sT + d) = f2h2(r2, r3);
            }
        }
    }
}

__global__ __launch_bounds__(256)
void attn_fused_kernel(const __half* __restrict__ q, const __half* __restrict__ k,
                       const __half* __restrict__ v,
                       __half* __restrict__ os, __half* __restrict__ ot)
{
    extern __shared__ __align__(16) char dynsm[];
    const int bid = blockIdx.x;
    if (bid < B_ * T_ * H_) {
        spatial_body(dynsm, bid, q, k, v, os);
    } else {
        temporal_body(dynsm, bid - B_ * T_ * H_, q, k, v, ot);
    }
}

// ---------------------------------------------------------------------------
extern "C" void kernel_launch(void* const* d_in, const int* in_sizes, int n_in,
                              void* d_out, int out_size)
{
    const float* x     = (const float*)d_in[0];
    const float* w_qkv = (const float*)d_in[1];
    const float* w_out = (const float*)d_in[2];
    const float* b_out = (const float*)d_in[3];
    float* out = (float*)d_out;

    __half *q, *k, *v, *os, *ot, *wqh, *woh;
    cudaGetSymbolAddress((void**)&q,   g_q);
    cudaGetSymbolAddress((void**)&k,   g_k);
    cudaGetSymbolAddress((void**)&v,   g_v);
    cudaGetSymbolAddress((void**)&os,  g_os);
    cudaGetSymbolAddress((void**)&ot,  g_ot);
    cudaGetSymbolAddress((void**)&wqh, g_wqh);
    cudaGetSymbolAddress((void**)&woh, g_woh);

    cudaFuncSetAttribute(gemm_qkv_kernel,
                         cudaFuncAttributeMaxDynamicSharedMemorySize, G1_SMEM);
    cudaFuncSetAttribute(gemm_out_kernel,
                         cudaFuncAttributeMaxDynamicSharedMemorySize, G2_SMEM);
    cudaFuncSetAttribute(attn_fused_kernel,
                         cudaFuncAttributeMaxDynamicSharedMemorySize, ATT_SMEM);

    // 0) convert weights to fp16 scratch
    {
        int total = (768 * 256 + 256 * 512) / 2;
        cvt_weights_kernel<<<(total + 255) / 256, 256>>>(w_qkv, w_out, wqh, woh);
    }
    // 1) QKV projection (head-major outputs) + fused q/k l2norm
    gemm_qkv_kernel<<<MTOK / 128, 256, G1_SMEM>>>(x, wqh, q, k, v);

    // 2+3) fused spatial + temporal attention (co-scheduled in one launch)
    attn_fused_kernel<<<B_ * T_ * H_ + B_ * N_, 256, ATT_SMEM>>>(q, k, v, os, ot);

    // 4) output projection + bias (head-major A operands)
    {
        dim3 grid(2, MTOK / 128);
        gemm_out_kernel<<<grid, 256, G2_SMEM>>>(os, ot, woh, b_out, out);
    }
}